// round 1
// baseline (speedup 1.0000x reference)
#include <cuda_runtime.h>
#include <math.h>
#include <math_constants.h>

#define BB 4
#define TT 2048
#define EE 1024
#define DD 128
#define M_TOT (BB*TT)

// Scratch (no allocations allowed)
__device__ float g_Q[M_TOT*DD];
__device__ float g_K[M_TOT*DD];
__device__ float g_V[M_TOT*DD];

// ---------------------------------------------------------------------------
// Projection: out = X @ W^T.  X:[8192,1024], W:[128,1024], out:[8192,128]
// One kernel, blockIdx.y selects which of Q/K/V weight it computes.
// 128x128 block tile, BK=8, 8x8 per thread, 256 threads.
// ---------------------------------------------------------------------------
#define PBM 128
#define PBK 8

__global__ __launch_bounds__(256)
void proj_kernel(const float* __restrict__ X,
                 const float* __restrict__ wQ,
                 const float* __restrict__ wK,
                 const float* __restrict__ wV)
{
    __shared__ float As[PBK][PBM];
    __shared__ float Bs[PBK][DD];

    const float* W;
    float* out;
    if (blockIdx.y == 0)      { W = wQ; out = g_Q; }
    else if (blockIdx.y == 1) { W = wK; out = g_K; }
    else                      { W = wV; out = g_V; }

    const int m0   = blockIdx.x * PBM;
    const int tid  = threadIdx.x;
    const int tx   = tid & 15;       // 0..15 -> n
    const int ty   = tid >> 4;       // 0..15 -> m
    const int lrow = tid >> 1;       // 0..127 (load row)
    const int lhal = tid & 1;        // 0/1   (which half of 8-wide k slice)

    float acc[8][8];
#pragma unroll
    for (int i = 0; i < 8; i++)
#pragma unroll
        for (int j = 0; j < 8; j++) acc[i][j] = 0.f;

    for (int k0 = 0; k0 < EE; k0 += PBK) {
        float4 a = *reinterpret_cast<const float4*>(&X[(size_t)(m0 + lrow) * EE + k0 + 4 * lhal]);
        float4 b = *reinterpret_cast<const float4*>(&W[(size_t)lrow * EE + k0 + 4 * lhal]);
        __syncthreads();
        As[4*lhal+0][lrow] = a.x; As[4*lhal+1][lrow] = a.y;
        As[4*lhal+2][lrow] = a.z; As[4*lhal+3][lrow] = a.w;
        Bs[4*lhal+0][lrow] = b.x; Bs[4*lhal+1][lrow] = b.y;
        Bs[4*lhal+2][lrow] = b.z; Bs[4*lhal+3][lrow] = b.w;
        __syncthreads();

#pragma unroll
        for (int kk = 0; kk < PBK; kk++) {
            float ar[8], br[8];
            *reinterpret_cast<float4*>(&ar[0]) = *reinterpret_cast<const float4*>(&As[kk][ty*8]);
            *reinterpret_cast<float4*>(&ar[4]) = *reinterpret_cast<const float4*>(&As[kk][ty*8+4]);
            *reinterpret_cast<float4*>(&br[0]) = *reinterpret_cast<const float4*>(&Bs[kk][tx*8]);
            *reinterpret_cast<float4*>(&br[4]) = *reinterpret_cast<const float4*>(&Bs[kk][tx*8+4]);
#pragma unroll
            for (int i = 0; i < 8; i++)
#pragma unroll
                for (int j = 0; j < 8; j++)
                    acc[i][j] = fmaf(ar[i], br[j], acc[i][j]);
        }
    }

#pragma unroll
    for (int i = 0; i < 8; i++) {
        size_t row = (size_t)(m0 + ty*8 + i);
        float4 o0 = make_float4(acc[i][0], acc[i][1], acc[i][2], acc[i][3]);
        float4 o1 = make_float4(acc[i][4], acc[i][5], acc[i][6], acc[i][7]);
        *reinterpret_cast<float4*>(&out[row * DD + tx*8])     = o0;
        *reinterpret_cast<float4*>(&out[row * DD + tx*8 + 4]) = o1;
    }
}

// ---------------------------------------------------------------------------
// RoPE on Q and K in place. One thread per (token, pair).
// freq_i = 10000^(-2i/128) = 2^(-i * 2*log2(10000)/128)
// ---------------------------------------------------------------------------
__global__ __launch_bounds__(256)
void rope_kernel()
{
    int idx = blockIdx.x * blockDim.x + threadIdx.x;   // [0, B*T*64)
    if (idx >= BB * TT * (DD/2)) return;
    int i = idx & 63;
    int t = (idx >> 6) & (TT - 1);
    float freq = exp2f(-0.20762050593046777f * (float)i);  // 2*log2(1e4)/128
    float ang = (float)t * freq;
    float s, c;
    sincosf(ang, &s, &c);

    size_t off = (size_t)idx * 2;
    float2 q = *reinterpret_cast<float2*>(&g_Q[off]);
    float2 k = *reinterpret_cast<float2*>(&g_K[off]);
    float2 qo, ko;
    qo.x = q.x * c - q.y * s;
    qo.y = q.x * s + q.y * c;
    ko.x = k.x * c - k.y * s;
    ko.y = k.x * s + k.y * c;
    *reinterpret_cast<float2*>(&g_Q[off]) = qo;
    *reinterpret_cast<float2*>(&g_K[off]) = ko;
}

// ---------------------------------------------------------------------------
// Flash attention, causal, pair-scheduled for load balance.
// Block: 256 threads = 32 rows x 8 parts (16 dims/part).
// K/V tiles of 64 rows x 128 dims in dynamic smem (64 KB).
// Block pb handles q-tiles pb and 63-pb (equal total work).
// ---------------------------------------------------------------------------
#define ABM 32
#define ABN 64
#define DP  16   // dims per part

extern __shared__ float attn_smem[];

__global__ __launch_bounds__(256)
void attn_kernel(float* __restrict__ out)
{
    float* Ks = attn_smem;              // [ABN][DD]
    float* Vs = attn_smem + ABN * DD;   // [ABN][DD]

    const int b    = blockIdx.x >> 5;   // 0..3
    const int pb   = blockIdx.x & 31;   // 0..31
    const int tid  = threadIdx.x;
    const int r    = tid >> 3;          // 0..31 row within q-tile
    const int part = tid & 7;           // 0..7
    const float scale = 0.08838834764831845f;  // 1/sqrt(128)

    for (int sel = 0; sel < 2; sel++) {
        const int qt = sel ? (63 - pb) : pb;
        const int q0 = qt * ABM;
        const int q  = q0 + r;

        float qreg[DP];
        {
            size_t qoff = ((size_t)(b * TT + q)) * DD + part * DP;
#pragma unroll
            for (int j = 0; j < DP/4; j++) {
                float4 v = *reinterpret_cast<const float4*>(&g_Q[qoff + 4*j]);
                qreg[4*j+0] = v.x; qreg[4*j+1] = v.y;
                qreg[4*j+2] = v.z; qreg[4*j+3] = v.w;
            }
        }

        float m = -CUDART_INF_F;
        float l = 0.f;
        float acc[DP];
#pragma unroll
        for (int j = 0; j < DP; j++) acc[j] = 0.f;

        const int nk = (q0 + ABM - 1) / ABN + 1;
        for (int kt = 0; kt < nk; kt++) {
            const int kbase = kt * ABN;
            __syncthreads();
            // cooperative tile load: 2048 float4 per tensor / 256 threads
            {
                const size_t gbase = ((size_t)(b * TT + kbase)) * DD;
#pragma unroll
                for (int i = 0; i < 8; i++) {
                    int idx = tid + i * 256;     // float4 index
                    float4 kv = *reinterpret_cast<const float4*>(&g_K[gbase + (size_t)idx * 4]);
                    *reinterpret_cast<float4*>(&Ks[idx * 4]) = kv;
                    float4 vv = *reinterpret_cast<const float4*>(&g_V[gbase + (size_t)idx * 4]);
                    *reinterpret_cast<float4*>(&Vs[idx * 4]) = vv;
                }
            }
            __syncthreads();

#pragma unroll 2
            for (int kk = 0; kk < ABN; kk++) {
                const int kg = kbase + kk;
                float s = 0.f;
                const float4* kp = reinterpret_cast<const float4*>(&Ks[kk * DD + part * DP]);
#pragma unroll
                for (int j = 0; j < DP/4; j++) {
                    float4 kv = kp[j];
                    s = fmaf(qreg[4*j+0], kv.x, s);
                    s = fmaf(qreg[4*j+1], kv.y, s);
                    s = fmaf(qreg[4*j+2], kv.z, s);
                    s = fmaf(qreg[4*j+3], kv.w, s);
                }
                s += __shfl_xor_sync(0xffffffff, s, 1);
                s += __shfl_xor_sync(0xffffffff, s, 2);
                s += __shfl_xor_sync(0xffffffff, s, 4);

                if (kg <= q) {
                    s *= scale;
                    float mnew = fmaxf(m, s);
                    if (mnew > m) {
                        float corr = __expf(m - mnew);
                        l *= corr;
#pragma unroll
                        for (int j = 0; j < DP; j++) acc[j] *= corr;
                        m = mnew;
                    }
                    float p = __expf(s - m);
                    l += p;
                    const float4* vp = reinterpret_cast<const float4*>(&Vs[kk * DD + part * DP]);
#pragma unroll
                    for (int j = 0; j < DP/4; j++) {
                        float4 vv = vp[j];
                        acc[4*j+0] = fmaf(p, vv.x, acc[4*j+0]);
                        acc[4*j+1] = fmaf(p, vv.y, acc[4*j+1]);
                        acc[4*j+2] = fmaf(p, vv.z, acc[4*j+2]);
                        acc[4*j+3] = fmaf(p, vv.w, acc[4*j+3]);
                    }
                }
            }
        }

        const float inv = 1.f / l;
        size_t ooff = ((size_t)(b * TT + q)) * DD + part * DP;
#pragma unroll
        for (int j = 0; j < DP/4; j++) {
            float4 o = make_float4(acc[4*j+0]*inv, acc[4*j+1]*inv,
                                   acc[4*j+2]*inv, acc[4*j+3]*inv);
            *reinterpret_cast<float4*>(&out[ooff + 4*j]) = o;
        }
    }
}

// ---------------------------------------------------------------------------
extern "C" void kernel_launch(void* const* d_in, const int* in_sizes, int n_in,
                              void* d_out, int out_size)
{
    const float* X  = (const float*)d_in[0];
    const float* wQ = (const float*)d_in[1];
    const float* wK = (const float*)d_in[2];
    const float* wV = (const float*)d_in[3];
    float* out = (float*)d_out;

    const int attn_smem_bytes = 2 * ABN * DD * (int)sizeof(float);  // 64 KB
    cudaFuncSetAttribute(attn_kernel, cudaFuncAttributeMaxDynamicSharedMemorySize,
                         attn_smem_bytes);

    proj_kernel<<<dim3(M_TOT / PBM, 3), 256>>>(X, wQ, wK, wV);
    rope_kernel<<<(BB * TT * (DD/2)) / 256, 256>>>();
    attn_kernel<<<BB * 32, 256, attn_smem_bytes>>>(out);
}

// round 2
// speedup vs baseline: 3.0365x; 3.0365x over previous
#include <cuda_runtime.h>
#include <math.h>
#include <math_constants.h>

#define BB 4
#define TT 2048
#define EE 1024
#define DD 128
#define M_TOT (BB*TT)

// Scratch (no allocations allowed)
__device__ float g_Q[M_TOT*DD];
__device__ float g_K[M_TOT*DD];
__device__ float g_V[M_TOT*DD];
__device__ float2 g_rope[TT*(DD/2)];   // cos/sin table [t][pair]

// ---------------------------------------------------------------------------
// RoPE table: angle = t * 10000^(-2i/128)
// ---------------------------------------------------------------------------
__global__ __launch_bounds__(256)
void rope_table_kernel()
{
    int idx = blockIdx.x * blockDim.x + threadIdx.x;   // [0, 2048*64)
    if (idx >= TT * (DD/2)) return;
    int i = idx & 63;
    int t = idx >> 6;
    float freq = exp2f(-0.20762050593046777f * (float)i);  // 2*log2(1e4)/128
    float ang = (float)t * freq;
    float s, c;
    sincosf(ang, &s, &c);
    g_rope[idx] = make_float2(c, s);
}

// ---------------------------------------------------------------------------
// Projection: out = X @ W^T, with RoPE fused into the epilogue for Q and K.
// X:[8192,1024], W:[128,1024], out:[8192,128]
// 128x128 block tile, BK=8, 8x8 per thread, 256 threads, 2 blocks/SM.
// ---------------------------------------------------------------------------
#define PBM 128
#define PBK 8

__global__ __launch_bounds__(256, 2)
void proj_kernel(const float* __restrict__ X,
                 const float* __restrict__ wQ,
                 const float* __restrict__ wK,
                 const float* __restrict__ wV)
{
    __shared__ float As[PBK][PBM];
    __shared__ float Bs[PBK][DD];

    const float* W;
    float* out;
    if (blockIdx.y == 0)      { W = wQ; out = g_Q; }
    else if (blockIdx.y == 1) { W = wK; out = g_K; }
    else                      { W = wV; out = g_V; }

    const int m0   = blockIdx.x * PBM;
    const int tid  = threadIdx.x;
    const int tx   = tid & 15;       // 0..15 -> n
    const int ty   = tid >> 4;       // 0..15 -> m
    const int lrow = tid >> 1;       // 0..127 (load row)
    const int lhal = tid & 1;        // 0/1   (which half of 8-wide k slice)

    float acc[8][8];
#pragma unroll
    for (int i = 0; i < 8; i++)
#pragma unroll
        for (int j = 0; j < 8; j++) acc[i][j] = 0.f;

    for (int k0 = 0; k0 < EE; k0 += PBK) {
        float4 a = *reinterpret_cast<const float4*>(&X[(size_t)(m0 + lrow) * EE + k0 + 4 * lhal]);
        float4 b = *reinterpret_cast<const float4*>(&W[(size_t)lrow * EE + k0 + 4 * lhal]);
        __syncthreads();
        As[4*lhal+0][lrow] = a.x; As[4*lhal+1][lrow] = a.y;
        As[4*lhal+2][lrow] = a.z; As[4*lhal+3][lrow] = a.w;
        Bs[4*lhal+0][lrow] = b.x; Bs[4*lhal+1][lrow] = b.y;
        Bs[4*lhal+2][lrow] = b.z; Bs[4*lhal+3][lrow] = b.w;
        __syncthreads();

#pragma unroll
        for (int kk = 0; kk < PBK; kk++) {
            float ar[8], br[8];
            *reinterpret_cast<float4*>(&ar[0]) = *reinterpret_cast<const float4*>(&As[kk][ty*8]);
            *reinterpret_cast<float4*>(&ar[4]) = *reinterpret_cast<const float4*>(&As[kk][ty*8+4]);
            *reinterpret_cast<float4*>(&br[0]) = *reinterpret_cast<const float4*>(&Bs[kk][tx*8]);
            *reinterpret_cast<float4*>(&br[4]) = *reinterpret_cast<const float4*>(&Bs[kk][tx*8+4]);
#pragma unroll
            for (int i = 0; i < 8; i++)
#pragma unroll
                for (int j = 0; j < 8; j++)
                    acc[i][j] = fmaf(ar[i], br[j], acc[i][j]);
        }
    }

    const bool do_rope = (blockIdx.y < 2);
#pragma unroll
    for (int i = 0; i < 8; i++) {
        size_t row = (size_t)(m0 + ty*8 + i);
        if (do_rope) {
            int t = (int)(row & (TT - 1));
#pragma unroll
            for (int p = 0; p < 4; p++) {
                float2 cs = g_rope[t * 64 + tx*4 + p];
                float x0 = acc[i][2*p], x1 = acc[i][2*p+1];
                acc[i][2*p]   = x0 * cs.x - x1 * cs.y;
                acc[i][2*p+1] = x0 * cs.y + x1 * cs.x;
            }
        }
        float4 o0 = make_float4(acc[i][0], acc[i][1], acc[i][2], acc[i][3]);
        float4 o1 = make_float4(acc[i][4], acc[i][5], acc[i][6], acc[i][7]);
        *reinterpret_cast<float4*>(&out[row * DD + tx*8])     = o0;
        *reinterpret_cast<float4*>(&out[row * DD + tx*8 + 4]) = o1;
    }
}

// ---------------------------------------------------------------------------
// Flash attention, causal, GEMM-style tiles.
// Block = 128 threads. Q tile 32 rows, K/V tile 64 keys, d = 128.
// S(32x64): 4x4 microtile (trow 0..7, tcol 0..15), outer product over d from
//   transposed Qs[d][row], Ks[d][key].
// Softmax on whole S tile (4 shuffles / row / 64 keys).
// O(32x128) += P(32x64)@V: 4 rows x 8 cols per thread, P broadcast from smem.
// Pair scheduling: block pb handles q-tiles pb and 63-pb (balanced ~33 tiles).
// ---------------------------------------------------------------------------
#define ABM 32
#define ABN 64
#define QS_STRIDE 36    // 32 + pad, float4-aligned
#define KS_STRIDE 68    // 64 + pad, float4-aligned
#define PS_STRIDE 68

#define SM_QS 0
#define SM_KS (SM_QS + DD*QS_STRIDE)              // 4608
#define SM_VS (SM_KS + DD*KS_STRIDE)              // 4608+8704 = 13312
#define SM_PS (SM_VS + ABN*DD)                    // +8192 = 21504
#define SM_FLOATS (SM_PS + ABM*PS_STRIDE)         // +2176 = 23680 (94720 B)

extern __shared__ float attn_sm[];

__global__ __launch_bounds__(128)
void attn_kernel(float* __restrict__ out)
{
    float* Qs = attn_sm + SM_QS;
    float* Ks = attn_sm + SM_KS;
    float* Vs = attn_sm + SM_VS;
    float* Ps = attn_sm + SM_PS;

    const int b    = blockIdx.x >> 5;   // 0..3
    const int pb   = blockIdx.x & 31;   // 0..31
    const int tid  = threadIdx.x;
    const int trow = tid >> 4;          // 0..7  (4 rows each)
    const int tcol = tid & 15;          // 0..15 (4 S-cols / 8 O-cols each)
    const float scale = 0.08838834764831845f;  // 1/sqrt(128)

    for (int sel = 0; sel < 2; sel++) {
        const int qt = sel ? (63 - pb) : pb;
        const int q0 = qt * ABM;

        __syncthreads();
        // Load Q tile transposed: Qs[d][row]
        {
            const int row  = tid & 31;
            const int dseg = tid >> 5;           // 0..3
            const size_t gq = ((size_t)(b * TT + q0 + row)) * DD + dseg * 32;
#pragma unroll
            for (int f = 0; f < 8; f++) {
                float4 v = *reinterpret_cast<const float4*>(&g_Q[gq + 4*f]);
                int d = dseg*32 + 4*f;
                Qs[(d+0)*QS_STRIDE + row] = v.x;
                Qs[(d+1)*QS_STRIDE + row] = v.y;
                Qs[(d+2)*QS_STRIDE + row] = v.z;
                Qs[(d+3)*QS_STRIDE + row] = v.w;
            }
        }

        float m[4], l[4], O[4][8];
#pragma unroll
        for (int i = 0; i < 4; i++) {
            m[i] = -CUDART_INF_F; l[i] = 0.f;
#pragma unroll
            for (int j = 0; j < 8; j++) O[i][j] = 0.f;
        }

        const int ntiles = (q0 + ABM + ABN - 1) / ABN;
        for (int kt = 0; kt < ntiles; kt++) {
            const int kbase = kt * ABN;
            __syncthreads();
            // Load K transposed Ks[d][key]; V natural Vs[key][d]
            {
                const int key  = tid & 63;
                const int dseg = tid >> 6;       // 0..1
                const size_t gk = ((size_t)(b * TT + kbase + key)) * DD + dseg * 64;
#pragma unroll
                for (int f = 0; f < 16; f++) {
                    float4 v = *reinterpret_cast<const float4*>(&g_K[gk + 4*f]);
                    int d = dseg*64 + 4*f;
                    Ks[(d+0)*KS_STRIDE + key] = v.x;
                    Ks[(d+1)*KS_STRIDE + key] = v.y;
                    Ks[(d+2)*KS_STRIDE + key] = v.z;
                    Ks[(d+3)*KS_STRIDE + key] = v.w;
                }
                const size_t gv = ((size_t)(b * TT + kbase)) * DD;
#pragma unroll
                for (int f = 0; f < 16; f++) {
                    int fi = tid + f * 128;
                    *reinterpret_cast<float4*>(&Vs[fi*4]) =
                        *reinterpret_cast<const float4*>(&g_V[gv + (size_t)fi*4]);
                }
            }
            __syncthreads();

            // S = Q @ K^T  (4x4 per thread)
            float S[4][4];
#pragma unroll
            for (int i = 0; i < 4; i++)
#pragma unroll
                for (int j = 0; j < 4; j++) S[i][j] = 0.f;

#pragma unroll 4
            for (int d = 0; d < DD; d++) {
                float4 ar = *reinterpret_cast<const float4*>(&Qs[d*QS_STRIDE + trow*4]);
                float4 br = *reinterpret_cast<const float4*>(&Ks[d*KS_STRIDE + tcol*4]);
                float a[4] = {ar.x, ar.y, ar.z, ar.w};
                float bb[4] = {br.x, br.y, br.z, br.w};
#pragma unroll
                for (int i = 0; i < 4; i++)
#pragma unroll
                    for (int j = 0; j < 4; j++)
                        S[i][j] = fmaf(a[i], bb[j], S[i][j]);
            }

            // scale + causal mask (only possible on last tile)
            if (kt == ntiles - 1) {
#pragma unroll
                for (int i = 0; i < 4; i++) {
                    int r = q0 + trow*4 + i;
#pragma unroll
                    for (int j = 0; j < 4; j++) {
                        int c = kbase + tcol*4 + j;
                        S[i][j] = (c > r) ? -CUDART_INF_F : S[i][j] * scale;
                    }
                }
            } else {
#pragma unroll
                for (int i = 0; i < 4; i++)
#pragma unroll
                    for (int j = 0; j < 4; j++) S[i][j] *= scale;
            }

            // online softmax per row (reduce across 16 threads sharing trow)
#pragma unroll
            for (int i = 0; i < 4; i++) {
                float rm = fmaxf(fmaxf(S[i][0], S[i][1]), fmaxf(S[i][2], S[i][3]));
                rm = fmaxf(rm, __shfl_xor_sync(0xffffffff, rm, 1));
                rm = fmaxf(rm, __shfl_xor_sync(0xffffffff, rm, 2));
                rm = fmaxf(rm, __shfl_xor_sync(0xffffffff, rm, 4));
                rm = fmaxf(rm, __shfl_xor_sync(0xffffffff, rm, 8));
                float mnew = fmaxf(m[i], rm);
                float corr = __expf(m[i] - mnew);
                m[i] = mnew;
                float p0 = __expf(S[i][0] - mnew);
                float p1 = __expf(S[i][1] - mnew);
                float p2 = __expf(S[i][2] - mnew);
                float p3 = __expf(S[i][3] - mnew);
                S[i][0] = p0; S[i][1] = p1; S[i][2] = p2; S[i][3] = p3;
                float rs = (p0 + p1) + (p2 + p3);
                rs += __shfl_xor_sync(0xffffffff, rs, 1);
                rs += __shfl_xor_sync(0xffffffff, rs, 2);
                rs += __shfl_xor_sync(0xffffffff, rs, 4);
                rs += __shfl_xor_sync(0xffffffff, rs, 8);
                l[i] = l[i] * corr + rs;
#pragma unroll
                for (int j = 0; j < 8; j++) O[i][j] *= corr;
                // write P row to smem
                *reinterpret_cast<float4*>(&Ps[(trow*4 + i)*PS_STRIDE + tcol*4]) =
                    make_float4(p0, p1, p2, p3);
            }
            __syncthreads();

            // O += P @ V   (4 rows x 8 cols per thread)
#pragma unroll 2
            for (int k = 0; k < ABN; k++) {
                float p[4];
#pragma unroll
                for (int i = 0; i < 4; i++)
                    p[i] = Ps[(trow*4 + i)*PS_STRIDE + k];   // warp broadcast
                float4 v0 = *reinterpret_cast<const float4*>(&Vs[k*DD + tcol*8]);
                float4 v1 = *reinterpret_cast<const float4*>(&Vs[k*DD + tcol*8 + 4]);
                float vv[8] = {v0.x, v0.y, v0.z, v0.w, v1.x, v1.y, v1.z, v1.w};
#pragma unroll
                for (int i = 0; i < 4; i++)
#pragma unroll
                    for (int j = 0; j < 8; j++)
                        O[i][j] = fmaf(p[i], vv[j], O[i][j]);
            }
        }

        // epilogue
#pragma unroll
        for (int i = 0; i < 4; i++) {
            float inv = 1.f / l[i];
            size_t ooff = ((size_t)(b * TT + q0 + trow*4 + i)) * DD + tcol*8;
            float4 o0 = make_float4(O[i][0]*inv, O[i][1]*inv, O[i][2]*inv, O[i][3]*inv);
            float4 o1 = make_float4(O[i][4]*inv, O[i][5]*inv, O[i][6]*inv, O[i][7]*inv);
            *reinterpret_cast<float4*>(&out[ooff])     = o0;
            *reinterpret_cast<float4*>(&out[ooff + 4]) = o1;
        }
    }
}

// ---------------------------------------------------------------------------
extern "C" void kernel_launch(void* const* d_in, const int* in_sizes, int n_in,
                              void* d_out, int out_size)
{
    const float* X  = (const float*)d_in[0];
    const float* wQ = (const float*)d_in[1];
    const float* wK = (const float*)d_in[2];
    const float* wV = (const float*)d_in[3];
    float* out = (float*)d_out;

    const int attn_smem_bytes = SM_FLOATS * (int)sizeof(float);  // ~92.5 KB
    cudaFuncSetAttribute(attn_kernel, cudaFuncAttributeMaxDynamicSharedMemorySize,
                         attn_smem_bytes);

    rope_table_kernel<<<(TT * (DD/2) + 255) / 256, 256>>>();
    proj_kernel<<<dim3(M_TOT / PBM, 3), 256>>>(X, wQ, wK, wV);
    attn_kernel<<<BB * 32, 128, attn_smem_bytes>>>(out);
}

// round 7
// speedup vs baseline: 3.6466x; 1.2009x over previous
#include <cuda_runtime.h>
#include <cuda_bf16.h>
#include <cstdint>
#include <math.h>
#include <math_constants.h>

#define BB 4
#define TT 2048
#define EE 1024
#define DD 128
#define M_TOT (BB*TT)

// Scratch (no allocations allowed)
__device__ float g_Q[M_TOT*DD];
__device__ float g_K[M_TOT*DD];
__device__ float g_V[M_TOT*DD];
__device__ float2 g_rope[TT*(DD/2)];   // cos/sin table [t][pair]

// ---------------------------------------------------------------------------
// Warp-MMA helpers (sm_80+ baseline PTX — legal on plain sm_100 target)
// ---------------------------------------------------------------------------
__device__ __forceinline__ uint32_t smem_u32(const void* p) {
    uint32_t a;
    asm("{ .reg .u64 t; cvta.to.shared.u64 t, %1; cvt.u32.u64 %0, t; }" : "=r"(a) : "l"(p));
    return a;
}
__device__ __forceinline__ void ldmx4(uint32_t* r, uint32_t addr) {
    asm volatile("ldmatrix.sync.aligned.m8n8.x4.shared.b16 {%0,%1,%2,%3}, [%4];"
        : "=r"(r[0]), "=r"(r[1]), "=r"(r[2]), "=r"(r[3]) : "r"(addr));
}
__device__ __forceinline__ void mma_bf16(float* c, const uint32_t* a, const uint32_t* b) {
    asm volatile("mma.sync.aligned.m16n8k16.row.col.f32.bf16.bf16.f32 "
        "{%0,%1,%2,%3}, {%4,%5,%6,%7}, {%8,%9}, {%0,%1,%2,%3};"
        : "+f"(c[0]), "+f"(c[1]), "+f"(c[2]), "+f"(c[3])
        : "r"(a[0]), "r"(a[1]), "r"(a[2]), "r"(a[3]), "r"(b[0]), "r"(b[1]));
}

__device__ __forceinline__ void split4(float4 v, uint2& hi, uint2& lo) {
    float f[4] = {v.x, v.y, v.z, v.w};
    unsigned short h[4], l[4];
#pragma unroll
    for (int i = 0; i < 4; i++) {
        __nv_bfloat16 bh = __float2bfloat16(f[i]);
        h[i] = __bfloat16_as_ushort(bh);
        float r = f[i] - __bfloat162float(bh);
        l[i] = __bfloat16_as_ushort(__float2bfloat16(r));
    }
    hi.x = (uint32_t)h[0] | ((uint32_t)h[1] << 16);
    hi.y = (uint32_t)h[2] | ((uint32_t)h[3] << 16);
    lo.x = (uint32_t)l[0] | ((uint32_t)l[1] << 16);
    lo.y = (uint32_t)l[2] | ((uint32_t)l[3] << 16);
}

// ---------------------------------------------------------------------------
// RoPE table
// ---------------------------------------------------------------------------
__global__ __launch_bounds__(256)
void rope_table_kernel()
{
    int idx = blockIdx.x * blockDim.x + threadIdx.x;
    if (idx >= TT * (DD/2)) return;
    int i = idx & 63;
    int t = idx >> 6;
    float freq = exp2f(-0.20762050593046777f * (float)i);
    float ang = (float)t * freq;
    float s, c;
    sincosf(ang, &s, &c);
    g_rope[idx] = make_float2(c, s);
}

// ===========================================================================
// Projection via mma.sync bf16 3-term split: out = X @ W^T, RoPE fused.
// grid (64 M-tiles, 3 weights), 256 threads = 8 warps (4x2).
// CTA tile 128(M) x 128(N), BK=32, double-buffered smem.
// Warp tile 32(M) x 64(N): 2 m16-frags x 8 n8-frags, 3 mma terms each.
// ===========================================================================
#define STR 40                          // bf16 elems per smem row (32 + pad)
#define TILE_ELEMS (128*STR)            // one operand tile (5120 bf16)
#define STAGE_ELEMS (4*TILE_ELEMS)      // Ah, Al, Bh, Bl
#define PROJ_SMEM_BYTES (2*STAGE_ELEMS*2)   // 2 stages x bf16 = 81920 B

extern __shared__ char proj_sm[];

__global__ __launch_bounds__(256)
void proj_mma_kernel(const float* __restrict__ X,
                     const float* __restrict__ wQ,
                     const float* __restrict__ wK,
                     const float* __restrict__ wV)
{
    const int tid  = threadIdx.x;
    const int wid  = tid >> 5;
    const int lane = tid & 31;
    const int m0   = blockIdx.x * 128;
    const int wsel = blockIdx.y;
    const float* W = (wsel == 0) ? wQ : (wsel == 1) ? wK : wV;
    float* outp    = (wsel == 0) ? g_Q : (wsel == 1) ? g_K : g_V;

    const int wm = wid >> 1;   // 0..3 -> M offset 32*wm
    const int wn = wid & 1;    // 0..1 -> N offset 64*wn

    const uint32_t sbase = smem_u32(proj_sm);
    __nv_bfloat16* sm16 = reinterpret_cast<__nv_bfloat16*>(proj_sm);

    // loader geometry: 256 threads cover 128 rows x 32 cols (fp32)
    const int lrow  = tid >> 1;        // 0..127
    const int lhalf = tid & 1;         // col base 16*lhalf

    float4 px[2][4], pw[2][4];
#pragma unroll
    for (int j = 0; j < 4; j++) {
        px[0][j] = *reinterpret_cast<const float4*>(&X[(size_t)(m0 + lrow) * EE + 16*lhalf + 4*j]);
        pw[0][j] = *reinterpret_cast<const float4*>(&W[(size_t)lrow * EE + 16*lhalf + 4*j]);
    }

    float acc[2][8][4];
#pragma unroll
    for (int mf = 0; mf < 2; mf++)
#pragma unroll
        for (int nf = 0; nf < 8; nf++)
#pragma unroll
            for (int q = 0; q < 4; q++) acc[mf][nf][q] = 0.f;

    for (int c = 0; c < 32; c++) {
        const int buf = c & 1;
        __nv_bfloat16* Ah = sm16 + buf * STAGE_ELEMS;
        __nv_bfloat16* Al = Ah + TILE_ELEMS;
        __nv_bfloat16* Bh = Ah + 2*TILE_ELEMS;
        __nv_bfloat16* Bl = Ah + 3*TILE_ELEMS;

        // convert + store this chunk
#pragma unroll
        for (int j = 0; j < 4; j++) {
            const int col = 16*lhalf + 4*j;
            uint2 hi, lo;
            split4(px[buf][j], hi, lo);
            *reinterpret_cast<uint2*>(&Ah[lrow*STR + col]) = hi;
            *reinterpret_cast<uint2*>(&Al[lrow*STR + col]) = lo;
            split4(pw[buf][j], hi, lo);
            *reinterpret_cast<uint2*>(&Bh[lrow*STR + col]) = hi;
            *reinterpret_cast<uint2*>(&Bl[lrow*STR + col]) = lo;
        }

        // prefetch next chunk (gmem -> regs), overlaps with MMA below
        if (c + 1 < 32) {
            const int k0 = (c + 1) * 32;
            const int nb = (c + 1) & 1;
#pragma unroll
            for (int j = 0; j < 4; j++) {
                px[nb][j] = *reinterpret_cast<const float4*>(&X[(size_t)(m0 + lrow) * EE + k0 + 16*lhalf + 4*j]);
                pw[nb][j] = *reinterpret_cast<const float4*>(&W[(size_t)lrow * EE + k0 + 16*lhalf + 4*j]);
            }
        }

        __syncthreads();

        const uint32_t stage = sbase + buf * (STAGE_ELEMS * 2);
#pragma unroll
        for (int kb = 0; kb < 32; kb += 16) {
            uint32_t ah[2][4], al[2][4];
#pragma unroll
            for (int mf = 0; mf < 2; mf++) {
                const int row = 32*wm + 16*mf + (lane & 15);
                const int col = kb + 8*(lane >> 4);
                const uint32_t addrA = stage + (uint32_t)(row*STR + col) * 2;
                ldmx4(ah[mf], addrA);
                ldmx4(al[mf], addrA + TILE_ELEMS*2);
            }
            uint32_t bh[8][2], bl[8][2];
#pragma unroll
            for (int nb4 = 0; nb4 < 4; nb4++) {
                const int n   = 64*wn + 16*nb4 + (lane & 7) + ((lane & 16) >> 1);
                const int col = kb + (lane & 8);
                const uint32_t addrB = stage + (uint32_t)(2*TILE_ELEMS + n*STR + col) * 2;
                uint32_t r[4];
                ldmx4(r, addrB);
                bh[2*nb4][0] = r[0]; bh[2*nb4][1] = r[1];
                bh[2*nb4+1][0] = r[2]; bh[2*nb4+1][1] = r[3];
                ldmx4(r, addrB + TILE_ELEMS*2);
                bl[2*nb4][0] = r[0]; bl[2*nb4][1] = r[1];
                bl[2*nb4+1][0] = r[2]; bl[2*nb4+1][1] = r[3];
            }
#pragma unroll
            for (int mf = 0; mf < 2; mf++)
#pragma unroll
                for (int nf = 0; nf < 8; nf++) {
                    mma_bf16(acc[mf][nf], ah[mf], bh[nf]);
                    mma_bf16(acc[mf][nf], ah[mf], bl[nf]);
                    mma_bf16(acc[mf][nf], al[mf], bh[nf]);
                }
        }
        __syncthreads();
    }

    // epilogue: RoPE (Q/K) + store
    const bool do_rope = (wsel < 2);
#pragma unroll
    for (int mf = 0; mf < 2; mf++) {
#pragma unroll
        for (int half = 0; half < 2; half++) {       // c0/c1 vs c2/c3 (row, row+8)
            const int row = m0 + 32*wm + 16*mf + (lane >> 2) + 8*half;
            const int t = row & (TT - 1);
#pragma unroll
            for (int nf = 0; nf < 8; nf++) {
                const int col = 64*wn + 8*nf + 2*(lane & 3);
                float x0 = acc[mf][nf][2*half];
                float x1 = acc[mf][nf][2*half + 1];
                if (do_rope) {
                    float2 cs = g_rope[t * 64 + (col >> 1)];
                    float r0 = x0 * cs.x - x1 * cs.y;
                    float r1 = x0 * cs.y + x1 * cs.x;
                    x0 = r0; x1 = r1;
                }
                *reinterpret_cast<float2*>(&outp[(size_t)row * DD + col]) = make_float2(x0, x1);
            }
        }
    }
}

// ---------------------------------------------------------------------------
// Flash attention (unchanged, proven): causal, GEMM-style tiles, pair-sched.
// ---------------------------------------------------------------------------
#define ABM 32
#define ABN 64
#define QS_STRIDE 36
#define KS_STRIDE 68
#define PS_STRIDE 68

#define SM_QS 0
#define SM_KS (SM_QS + DD*QS_STRIDE)
#define SM_VS (SM_KS + DD*KS_STRIDE)
#define SM_PS (SM_VS + ABN*DD)
#define SM_FLOATS (SM_PS + ABM*PS_STRIDE)

extern __shared__ float attn_sm[];

__global__ __launch_bounds__(128)
void attn_kernel(float* __restrict__ out)
{
    float* Qs = attn_sm + SM_QS;
    float* Ks = attn_sm + SM_KS;
    float* Vs = attn_sm + SM_VS;
    float* Ps = attn_sm + SM_PS;

    const int b    = blockIdx.x >> 5;
    const int pb   = blockIdx.x & 31;
    const int tid  = threadIdx.x;
    const int trow = tid >> 4;
    const int tcol = tid & 15;
    const float scale = 0.08838834764831845f;

    for (int sel = 0; sel < 2; sel++) {
        const int qt = sel ? (63 - pb) : pb;
        const int q0 = qt * ABM;

        __syncthreads();
        {
            const int row  = tid & 31;
            const int dseg = tid >> 5;
            const size_t gq = ((size_t)(b * TT + q0 + row)) * DD + dseg * 32;
#pragma unroll
            for (int f = 0; f < 8; f++) {
                float4 v = *reinterpret_cast<const float4*>(&g_Q[gq + 4*f]);
                int d = dseg*32 + 4*f;
                Qs[(d+0)*QS_STRIDE + row] = v.x;
                Qs[(d+1)*QS_STRIDE + row] = v.y;
                Qs[(d+2)*QS_STRIDE + row] = v.z;
                Qs[(d+3)*QS_STRIDE + row] = v.w;
            }
        }

        float m[4], l[4], O[4][8];
#pragma unroll
        for (int i = 0; i < 4; i++) {
            m[i] = -CUDART_INF_F; l[i] = 0.f;
#pragma unroll
            for (int j = 0; j < 8; j++) O[i][j] = 0.f;
        }

        const int ntiles = (q0 + ABM + ABN - 1) / ABN;
        for (int kt = 0; kt < ntiles; kt++) {
            const int kbase = kt * ABN;
            __syncthreads();
            {
                const int key  = tid & 63;
                const int dseg = tid >> 6;
                const size_t gk = ((size_t)(b * TT + kbase + key)) * DD + dseg * 64;
#pragma unroll
                for (int f = 0; f < 16; f++) {
                    float4 v = *reinterpret_cast<const float4*>(&g_K[gk + 4*f]);
                    int d = dseg*64 + 4*f;
                    Ks[(d+0)*KS_STRIDE + key] = v.x;
                    Ks[(d+1)*KS_STRIDE + key] = v.y;
                    Ks[(d+2)*KS_STRIDE + key] = v.z;
                    Ks[(d+3)*KS_STRIDE + key] = v.w;
                }
                const size_t gv = ((size_t)(b * TT + kbase)) * DD;
#pragma unroll
                for (int f = 0; f < 16; f++) {
                    int fi = tid + f * 128;
                    *reinterpret_cast<float4*>(&Vs[fi*4]) =
                        *reinterpret_cast<const float4*>(&g_V[gv + (size_t)fi*4]);
                }
            }
            __syncthreads();

            float S[4][4];
#pragma unroll
            for (int i = 0; i < 4; i++)
#pragma unroll
                for (int j = 0; j < 4; j++) S[i][j] = 0.f;

#pragma unroll 4
            for (int d = 0; d < DD; d++) {
                float4 ar = *reinterpret_cast<const float4*>(&Qs[d*QS_STRIDE + trow*4]);
                float4 br = *reinterpret_cast<const float4*>(&Ks[d*KS_STRIDE + tcol*4]);
                float a[4] = {ar.x, ar.y, ar.z, ar.w};
                float bb[4] = {br.x, br.y, br.z, br.w};
#pragma unroll
                for (int i = 0; i < 4; i++)
#pragma unroll
                    for (int j = 0; j < 4; j++)
                        S[i][j] = fmaf(a[i], bb[j], S[i][j]);
            }

            if (kt == ntiles - 1) {
#pragma unroll
                for (int i = 0; i < 4; i++) {
                    int r = q0 + trow*4 + i;
#pragma unroll
                    for (int j = 0; j < 4; j++) {
                        int c = kbase + tcol*4 + j;
                        S[i][j] = (c > r) ? -CUDART_INF_F : S[i][j] * scale;
                    }
                }
            } else {
#pragma unroll
                for (int i = 0; i < 4; i++)
#pragma unroll
                    for (int j = 0; j < 4; j++) S[i][j] *= scale;
            }

#pragma unroll
            for (int i = 0; i < 4; i++) {
                float rm = fmaxf(fmaxf(S[i][0], S[i][1]), fmaxf(S[i][2], S[i][3]));
                rm = fmaxf(rm, __shfl_xor_sync(0xffffffff, rm, 1));
                rm = fmaxf(rm, __shfl_xor_sync(0xffffffff, rm, 2));
                rm = fmaxf(rm, __shfl_xor_sync(0xffffffff, rm, 4));
                rm = fmaxf(rm, __shfl_xor_sync(0xffffffff, rm, 8));
                float mnew = fmaxf(m[i], rm);
                float corr = __expf(m[i] - mnew);
                m[i] = mnew;
                float p0 = __expf(S[i][0] - mnew);
                float p1 = __expf(S[i][1] - mnew);
                float p2 = __expf(S[i][2] - mnew);
                float p3 = __expf(S[i][3] - mnew);
                float rs = (p0 + p1) + (p2 + p3);
                rs += __shfl_xor_sync(0xffffffff, rs, 1);
                rs += __shfl_xor_sync(0xffffffff, rs, 2);
                rs += __shfl_xor_sync(0xffffffff, rs, 4);
                rs += __shfl_xor_sync(0xffffffff, rs, 8);
                l[i] = l[i] * corr + rs;
#pragma unroll
                for (int j = 0; j < 8; j++) O[i][j] *= corr;
                *reinterpret_cast<float4*>(&Ps[(trow*4 + i)*PS_STRIDE + tcol*4]) =
                    make_float4(p0, p1, p2, p3);
            }
            __syncthreads();

#pragma unroll 2
            for (int k = 0; k < ABN; k++) {
                float p[4];
#pragma unroll
                for (int i = 0; i < 4; i++)
                    p[i] = Ps[(trow*4 + i)*PS_STRIDE + k];
                float4 v0 = *reinterpret_cast<const float4*>(&Vs[k*DD + tcol*8]);
                float4 v1 = *reinterpret_cast<const float4*>(&Vs[k*DD + tcol*8 + 4]);
                float vv[8] = {v0.x, v0.y, v0.z, v0.w, v1.x, v1.y, v1.z, v1.w};
#pragma unroll
                for (int i = 0; i < 4; i++)
#pragma unroll
                    for (int j = 0; j < 8; j++)
                        O[i][j] = fmaf(p[i], vv[j], O[i][j]);
            }
        }

#pragma unroll
        for (int i = 0; i < 4; i++) {
            float inv = 1.f / l[i];
            size_t ooff = ((size_t)(b * TT + q0 + trow*4 + i)) * DD + tcol*8;
            float4 o0 = make_float4(O[i][0]*inv, O[i][1]*inv, O[i][2]*inv, O[i][3]*inv);
            float4 o1 = make_float4(O[i][4]*inv, O[i][5]*inv, O[i][6]*inv, O[i][7]*inv);
            *reinterpret_cast<float4*>(&out[ooff])     = o0;
            *reinterpret_cast<float4*>(&out[ooff + 4]) = o1;
        }
    }
}

// ---------------------------------------------------------------------------
extern "C" void kernel_launch(void* const* d_in, const int* in_sizes, int n_in,
                              void* d_out, int out_size)
{
    const float* X  = (const float*)d_in[0];
    const float* wQ = (const float*)d_in[1];
    const float* wK = (const float*)d_in[2];
    const float* wV = (const float*)d_in[3];
    float* out = (float*)d_out;

    const int attn_smem_bytes = SM_FLOATS * (int)sizeof(float);
    cudaFuncSetAttribute(attn_kernel, cudaFuncAttributeMaxDynamicSharedMemorySize,
                         attn_smem_bytes);
    cudaFuncSetAttribute(proj_mma_kernel, cudaFuncAttributeMaxDynamicSharedMemorySize,
                         PROJ_SMEM_BYTES);

    rope_table_kernel<<<(TT * (DD/2) + 255) / 256, 256>>>();
    proj_mma_kernel<<<dim3(M_TOT / 128, 3), 256, PROJ_SMEM_BYTES>>>(X, wQ, wK, wV);
    attn_kernel<<<BB * 32, 128, attn_smem_bytes>>>(out);
}

// round 8
// speedup vs baseline: 5.0080x; 1.3733x over previous
#include <cuda_runtime.h>
#include <cuda_bf16.h>
#include <cstdint>
#include <math.h>
#include <math_constants.h>

#define BB 4
#define TT 2048
#define EE 1024
#define DD 128
#define M_TOT (BB*TT)

// Split bf16 operands (written by proj, read by attention). 2 MB each.
__device__ __nv_bfloat16 g_Qh[M_TOT*DD];
__device__ __nv_bfloat16 g_Ql[M_TOT*DD];
__device__ __nv_bfloat16 g_Kh[M_TOT*DD];
__device__ __nv_bfloat16 g_Kl[M_TOT*DD];
__device__ __nv_bfloat16 g_Vh[M_TOT*DD];
__device__ __nv_bfloat16 g_Vl[M_TOT*DD];
__device__ float2 g_rope[TT*(DD/2)];   // cos/sin table [t][pair]

// ---------------------------------------------------------------------------
// Warp-MMA helpers (sm_80+ baseline PTX — legal on plain sm_100 target)
// ---------------------------------------------------------------------------
__device__ __forceinline__ uint32_t smem_u32(const void* p) {
    uint32_t a;
    asm("{ .reg .u64 t; cvta.to.shared.u64 t, %1; cvt.u32.u64 %0, t; }" : "=r"(a) : "l"(p));
    return a;
}
__device__ __forceinline__ void ldmx4(uint32_t* r, uint32_t addr) {
    asm volatile("ldmatrix.sync.aligned.m8n8.x4.shared.b16 {%0,%1,%2,%3}, [%4];"
        : "=r"(r[0]), "=r"(r[1]), "=r"(r[2]), "=r"(r[3]) : "r"(addr));
}
__device__ __forceinline__ void ldmx4t(uint32_t* r, uint32_t addr) {
    asm volatile("ldmatrix.sync.aligned.m8n8.x4.trans.shared.b16 {%0,%1,%2,%3}, [%4];"
        : "=r"(r[0]), "=r"(r[1]), "=r"(r[2]), "=r"(r[3]) : "r"(addr));
}
__device__ __forceinline__ void mma_bf16(float* c, const uint32_t* a, const uint32_t* b) {
    asm volatile("mma.sync.aligned.m16n8k16.row.col.f32.bf16.bf16.f32 "
        "{%0,%1,%2,%3}, {%4,%5,%6,%7}, {%8,%9}, {%0,%1,%2,%3};"
        : "+f"(c[0]), "+f"(c[1]), "+f"(c[2]), "+f"(c[3])
        : "r"(a[0]), "r"(a[1]), "r"(a[2]), "r"(a[3]), "r"(b[0]), "r"(b[1]));
}
#define CP16(dst, src) \
    asm volatile("cp.async.cg.shared.global [%0], [%1], 16;" :: "r"(dst), "l"(src))
#define CPCOMMIT() asm volatile("cp.async.commit_group;" ::: "memory")
#define CPWAIT1()  asm volatile("cp.async.wait_group 1;" ::: "memory")

__device__ __forceinline__ void split4(float4 v, uint2& hi, uint2& lo) {
    float f[4] = {v.x, v.y, v.z, v.w};
    unsigned short h[4], l[4];
#pragma unroll
    for (int i = 0; i < 4; i++) {
        __nv_bfloat16 bh = __float2bfloat16(f[i]);
        h[i] = __bfloat16_as_ushort(bh);
        float r = f[i] - __bfloat162float(bh);
        l[i] = __bfloat16_as_ushort(__float2bfloat16(r));
    }
    hi.x = (uint32_t)h[0] | ((uint32_t)h[1] << 16);
    hi.y = (uint32_t)h[2] | ((uint32_t)h[3] << 16);
    lo.x = (uint32_t)l[0] | ((uint32_t)l[1] << 16);
    lo.y = (uint32_t)l[2] | ((uint32_t)l[3] << 16);
}
__device__ __forceinline__ uint32_t pack2h(float a, float b, uint32_t& lo) {
    __nv_bfloat16 ah = __float2bfloat16(a), bh = __float2bfloat16(b);
    float ar = a - __bfloat162float(ah), br = b - __bfloat162float(bh);
    lo = (uint32_t)__bfloat16_as_ushort(__float2bfloat16(ar))
       | ((uint32_t)__bfloat16_as_ushort(__float2bfloat16(br)) << 16);
    return (uint32_t)__bfloat16_as_ushort(ah) | ((uint32_t)__bfloat16_as_ushort(bh) << 16);
}

// swizzled byte offset inside a 128-col bf16 tile (256 B rows)
__device__ __forceinline__ uint32_t swz(uint32_t row, uint32_t col) {
    return row*256u + ((((col>>3) ^ (row&7)))<<4) + (col&7)*2u;
}
// swizzled byte offset inside a 64-col bf16 tile (128 B rows)
__device__ __forceinline__ uint32_t swzP(uint32_t row, uint32_t col) {
    return row*128u + ((((col>>3) ^ (row&7)))<<4) + (col&7)*2u;
}

// ---------------------------------------------------------------------------
// RoPE table
// ---------------------------------------------------------------------------
__global__ __launch_bounds__(256)
void rope_table_kernel()
{
    int idx = blockIdx.x * blockDim.x + threadIdx.x;
    if (idx >= TT * (DD/2)) return;
    int i = idx & 63;
    int t = idx >> 6;
    float freq = exp2f(-0.20762050593046777f * (float)i);
    float ang = (float)t * freq;
    float s, c;
    sincosf(ang, &s, &c);
    g_rope[idx] = make_float2(c, s);
}

// ===========================================================================
// Projection via mma.sync bf16 3-term split; RoPE fused; writes split bf16.
// ===========================================================================
#define STR 40
#define TILE_ELEMS (128*STR)
#define STAGE_ELEMS (4*TILE_ELEMS)
#define PROJ_SMEM_BYTES (2*STAGE_ELEMS*2)

extern __shared__ char proj_sm[];

__global__ __launch_bounds__(256)
void proj_mma_kernel(const float* __restrict__ X,
                     const float* __restrict__ wQ,
                     const float* __restrict__ wK,
                     const float* __restrict__ wV)
{
    const int tid  = threadIdx.x;
    const int wid  = tid >> 5;
    const int lane = tid & 31;
    const int m0   = blockIdx.x * 128;
    const int wsel = blockIdx.y;
    const float* W = (wsel == 0) ? wQ : (wsel == 1) ? wK : wV;
    __nv_bfloat16* oh = (wsel == 0) ? g_Qh : (wsel == 1) ? g_Kh : g_Vh;
    __nv_bfloat16* ol = (wsel == 0) ? g_Ql : (wsel == 1) ? g_Kl : g_Vl;

    const int wm = wid >> 1;
    const int wn = wid & 1;

    const uint32_t sbase = smem_u32(proj_sm);
    __nv_bfloat16* sm16 = reinterpret_cast<__nv_bfloat16*>(proj_sm);

    const int lrow  = tid >> 1;
    const int lhalf = tid & 1;

    float4 px[2][4], pw[2][4];
#pragma unroll
    for (int j = 0; j < 4; j++) {
        px[0][j] = *reinterpret_cast<const float4*>(&X[(size_t)(m0 + lrow) * EE + 16*lhalf + 4*j]);
        pw[0][j] = *reinterpret_cast<const float4*>(&W[(size_t)lrow * EE + 16*lhalf + 4*j]);
    }

    float acc[2][8][4];
#pragma unroll
    for (int mf = 0; mf < 2; mf++)
#pragma unroll
        for (int nf = 0; nf < 8; nf++)
#pragma unroll
            for (int q = 0; q < 4; q++) acc[mf][nf][q] = 0.f;

    for (int c = 0; c < 32; c++) {
        const int buf = c & 1;
        __nv_bfloat16* Ah = sm16 + buf * STAGE_ELEMS;
        __nv_bfloat16* Al = Ah + TILE_ELEMS;
        __nv_bfloat16* Bh = Ah + 2*TILE_ELEMS;
        __nv_bfloat16* Bl = Ah + 3*TILE_ELEMS;

#pragma unroll
        for (int j = 0; j < 4; j++) {
            const int col = 16*lhalf + 4*j;
            uint2 hi, lo;
            split4(px[buf][j], hi, lo);
            *reinterpret_cast<uint2*>(&Ah[lrow*STR + col]) = hi;
            *reinterpret_cast<uint2*>(&Al[lrow*STR + col]) = lo;
            split4(pw[buf][j], hi, lo);
            *reinterpret_cast<uint2*>(&Bh[lrow*STR + col]) = hi;
            *reinterpret_cast<uint2*>(&Bl[lrow*STR + col]) = lo;
        }

        if (c + 1 < 32) {
            const int k0 = (c + 1) * 32;
            const int nb = (c + 1) & 1;
#pragma unroll
            for (int j = 0; j < 4; j++) {
                px[nb][j] = *reinterpret_cast<const float4*>(&X[(size_t)(m0 + lrow) * EE + k0 + 16*lhalf + 4*j]);
                pw[nb][j] = *reinterpret_cast<const float4*>(&W[(size_t)lrow * EE + k0 + 16*lhalf + 4*j]);
            }
        }

        __syncthreads();

        const uint32_t stage = sbase + buf * (STAGE_ELEMS * 2);
#pragma unroll
        for (int kb = 0; kb < 32; kb += 16) {
            uint32_t ah[2][4], al[2][4];
#pragma unroll
            for (int mf = 0; mf < 2; mf++) {
                const int row = 32*wm + 16*mf + (lane & 15);
                const int col = kb + 8*(lane >> 4);
                const uint32_t addrA = stage + (uint32_t)(row*STR + col) * 2;
                ldmx4(ah[mf], addrA);
                ldmx4(al[mf], addrA + TILE_ELEMS*2);
            }
            uint32_t bh[8][2], bl[8][2];
#pragma unroll
            for (int nb4 = 0; nb4 < 4; nb4++) {
                const int n   = 64*wn + 16*nb4 + (lane & 7) + ((lane & 16) >> 1);
                const int col = kb + (lane & 8);
                const uint32_t addrB = stage + (uint32_t)(2*TILE_ELEMS + n*STR + col) * 2;
                uint32_t r[4];
                ldmx4(r, addrB);
                bh[2*nb4][0] = r[0]; bh[2*nb4][1] = r[1];
                bh[2*nb4+1][0] = r[2]; bh[2*nb4+1][1] = r[3];
                ldmx4(r, addrB + TILE_ELEMS*2);
                bl[2*nb4][0] = r[0]; bl[2*nb4][1] = r[1];
                bl[2*nb4+1][0] = r[2]; bl[2*nb4+1][1] = r[3];
            }
#pragma unroll
            for (int mf = 0; mf < 2; mf++)
#pragma unroll
                for (int nf = 0; nf < 8; nf++) {
                    mma_bf16(acc[mf][nf], ah[mf], bh[nf]);
                    mma_bf16(acc[mf][nf], ah[mf], bl[nf]);
                    mma_bf16(acc[mf][nf], al[mf], bh[nf]);
                }
        }
        __syncthreads();
    }

    // epilogue: RoPE (Q/K), split, store bf16 h/l
    const bool do_rope = (wsel < 2);
#pragma unroll
    for (int mf = 0; mf < 2; mf++) {
#pragma unroll
        for (int half = 0; half < 2; half++) {
            const int row = m0 + 32*wm + 16*mf + (lane >> 2) + 8*half;
            const int t = row & (TT - 1);
#pragma unroll
            for (int nf = 0; nf < 8; nf++) {
                const int col = 64*wn + 8*nf + 2*(lane & 3);
                float x0 = acc[mf][nf][2*half];
                float x1 = acc[mf][nf][2*half + 1];
                if (do_rope) {
                    float2 cs = g_rope[t * 64 + (col >> 1)];
                    float r0 = x0 * cs.x - x1 * cs.y;
                    float r1 = x0 * cs.y + x1 * cs.x;
                    x0 = r0; x1 = r1;
                }
                uint32_t lo;
                uint32_t hi = pack2h(x0, x1, lo);
                *reinterpret_cast<uint32_t*>(&oh[(size_t)row * DD + col]) = hi;
                *reinterpret_cast<uint32_t*>(&ol[(size_t)row * DD + col]) = lo;
            }
        }
    }
}

// ===========================================================================
// Tensor-core flash attention. BM=32, BN=64, 128 threads (4 warps).
// S: warps split keys 4x16; PV: warps split D 4x32. cp.async double-buffered.
// ===========================================================================
#define A_QH 0
#define A_QL 8192
#define A_K  16384              // + buf*32768 ; +16384 for low part
#define A_V  81920              // + buf*32768 ; +16384 for low part
#define A_PH 147456
#define A_PL 151552
#define A_MAX 155648
#define A_SUM 156160
#define ATTN_SMEM 156672

extern __shared__ char attn_smc[];

__device__ __forceinline__ void issue_kv(uint32_t sb, int buf, int tid,
                                         const __nv_bfloat16* Kh, const __nv_bfloat16* Kl,
                                         const __nv_bfloat16* Vh, const __nv_bfloat16* Vl,
                                         int kbase)
{
    const int row = tid >> 1;
    const int ch0 = (tid & 1) * 8;
    const size_t gb = ((size_t)(kbase + row)) * DD;
    const uint32_t kb = sb + A_K + buf * 32768;
    const uint32_t vb = sb + A_V + buf * 32768;
#pragma unroll
    for (int j = 0; j < 8; j++) {
        const int ch = ch0 + j;
        const uint32_t d = swz(row, ch * 8);
        CP16(kb + d,         Kh + gb + ch*8);
        CP16(kb + 16384 + d, Kl + gb + ch*8);
        CP16(vb + d,         Vh + gb + ch*8);
        CP16(vb + 16384 + d, Vl + gb + ch*8);
    }
}

__global__ __launch_bounds__(128)
void attn_mma_kernel(float* __restrict__ out)
{
    const uint32_t sb = smem_u32(attn_smc);
    const int tid  = threadIdx.x;
    const int wid  = tid >> 5;
    const int lane = tid & 31;
    const int b    = blockIdx.x >> 5;
    const int pb   = blockIdx.x & 31;
    const float scale = 0.08838834764831845f;

    const __nv_bfloat16* Qh = g_Qh + (size_t)b*TT*DD;
    const __nv_bfloat16* Ql = g_Ql + (size_t)b*TT*DD;
    const __nv_bfloat16* Kh = g_Kh + (size_t)b*TT*DD;
    const __nv_bfloat16* Kl = g_Kl + (size_t)b*TT*DD;
    const __nv_bfloat16* Vh = g_Vh + (size_t)b*TT*DD;
    const __nv_bfloat16* Vl = g_Vl + (size_t)b*TT*DD;

    float* maxs = reinterpret_cast<float*>(attn_smc + A_MAX);
    float* sums = reinterpret_cast<float*>(attn_smc + A_SUM);

    for (int sel = 0; sel < 2; sel++) {
        const int q0 = (sel ? (63 - pb) : pb) * 32;
        const int ntiles = q0 / 64 + 1;

        // load Q tile (h/l) into swizzled smem
        {
            const int row = tid >> 2;
            const int cb  = (tid & 3) * 4;
            const size_t gq = ((size_t)(q0 + row)) * DD;
#pragma unroll
            for (int j = 0; j < 4; j++) {
                const int ch = cb + j;
                const uint32_t d = swz(row, ch * 8);
                *reinterpret_cast<uint4*>(attn_smc + A_QH + d) =
                    *reinterpret_cast<const uint4*>(Qh + gq + ch*8);
                *reinterpret_cast<uint4*>(attn_smc + A_QL + d) =
                    *reinterpret_cast<const uint4*>(Ql + gq + ch*8);
            }
        }
        issue_kv(sb, 0, tid, Kh, Kl, Vh, Vl, 0);
        CPCOMMIT();
        if (ntiles > 1) issue_kv(sb, 1, tid, Kh, Kl, Vh, Vl, 64);
        CPCOMMIT();
        __syncthreads();

        float mst[4], lst[4], O[2][4][4];
#pragma unroll
        for (int s = 0; s < 4; s++) { mst[s] = -CUDART_INF_F; lst[s] = 0.f; }
#pragma unroll
        for (int mf = 0; mf < 2; mf++)
#pragma unroll
            for (int nf = 0; nf < 4; nf++)
#pragma unroll
                for (int q = 0; q < 4; q++) O[mf][nf][q] = 0.f;

        for (int t = 0; t < ntiles; t++) {
            const int buf = t & 1;
            const int kbase = t * 64;
            const uint32_t kBufH = sb + A_K + buf*32768;
            const uint32_t kBufL = kBufH + 16384;
            const uint32_t vBufH = sb + A_V + buf*32768;
            const uint32_t vBufL = vBufH + 16384;

            CPWAIT1();
            __syncthreads();

            // ---- S = Qh*Kh + Qh*Kl + Ql*Kh ----
            float S[2][2][4];
#pragma unroll
            for (int mf = 0; mf < 2; mf++)
#pragma unroll
                for (int nf = 0; nf < 2; nf++)
#pragma unroll
                    for (int q = 0; q < 4; q++) S[mf][nf][q] = 0.f;

            const int aRow = lane & 15;
            const int aCol = 8 * (lane >> 4);
            const int bRow = 16*wid + (lane & 7) + ((lane & 16) >> 1);
            const int bCol = lane & 8;
#pragma unroll
            for (int kc = 0; kc < 8; kc++) {
                uint32_t qh0[4], qh1[4], ql0[4], ql1[4];
                const uint32_t a0 = swz(aRow,      kc*16 + aCol);
                const uint32_t a1 = swz(16 + aRow, kc*16 + aCol);
                ldmx4(qh0, sb + A_QH + a0);
                ldmx4(qh1, sb + A_QH + a1);
                ldmx4(ql0, sb + A_QL + a0);
                ldmx4(ql1, sb + A_QL + a1);
                uint32_t rb[4], kbh[2][2], kbl[2][2];
                const uint32_t ba = swz(bRow, kc*16 + bCol);
                ldmx4(rb, kBufH + ba);
                kbh[0][0]=rb[0]; kbh[0][1]=rb[1]; kbh[1][0]=rb[2]; kbh[1][1]=rb[3];
                ldmx4(rb, kBufL + ba);
                kbl[0][0]=rb[0]; kbl[0][1]=rb[1]; kbl[1][0]=rb[2]; kbl[1][1]=rb[3];
#pragma unroll
                for (int nf = 0; nf < 2; nf++) {
                    mma_bf16(S[0][nf], qh0, kbh[nf]);
                    mma_bf16(S[0][nf], qh0, kbl[nf]);
                    mma_bf16(S[0][nf], ql0, kbh[nf]);
                    mma_bf16(S[1][nf], qh1, kbh[nf]);
                    mma_bf16(S[1][nf], qh1, kbl[nf]);
                    mma_bf16(S[1][nf], ql1, kbh[nf]);
                }
            }

            // ---- mask + scale ----
            const bool lastt = (t == ntiles - 1);
#pragma unroll
            for (int mf = 0; mf < 2; mf++)
#pragma unroll
                for (int nf = 0; nf < 2; nf++)
#pragma unroll
                    for (int q = 0; q < 4; q++) {
                        const int gcol = kbase + 16*wid + 8*nf + 2*(lane & 3) + (q & 1);
                        const int grow = q0 + (lane >> 2) + 8*(q >> 1) + 16*mf;
                        if (lastt && gcol > grow) S[mf][nf][q] = -1e30f;
                        else S[mf][nf][q] *= scale;
                    }

            // ---- partial row max -> smem ----
            float pm[4];
#pragma unroll
            for (int s = 0; s < 4; s++) {
                const int mf = s >> 1, h = s & 1;
                float v = fmaxf(fmaxf(S[mf][0][2*h], S[mf][0][2*h+1]),
                                fmaxf(S[mf][1][2*h], S[mf][1][2*h+1]));
                v = fmaxf(v, __shfl_xor_sync(0xffffffff, v, 1));
                v = fmaxf(v, __shfl_xor_sync(0xffffffff, v, 2));
                pm[s] = v;
            }
            if ((lane & 3) == 0) {
#pragma unroll
                for (int s = 0; s < 4; s++) {
                    const int row = (lane >> 2) + 8*(s & 1) + 16*(s >> 1);
                    maxs[row*4 + wid] = pm[s];
                }
            }
            __syncthreads();

            // ---- global max, p=exp, write P, partial sums ----
            float corr[4], rs[4];
#pragma unroll
            for (int s = 0; s < 4; s++) {
                const int row = (lane >> 2) + 8*(s & 1) + 16*(s >> 1);
                float4 mp = *reinterpret_cast<float4*>(&maxs[row*4]);
                float mn = fmaxf(fmaxf(mp.x, mp.y), fmaxf(mp.z, mp.w));
                float mnew = fmaxf(mst[s], mn);
                corr[s] = __expf(mst[s] - mnew);
                mst[s] = mnew;
                rs[s] = 0.f;
            }
#pragma unroll
            for (int mf = 0; mf < 2; mf++)
#pragma unroll
                for (int nf = 0; nf < 2; nf++)
#pragma unroll
                    for (int h = 0; h < 2; h++) {
                        const int s = mf*2 + h;
                        float p0 = __expf(S[mf][nf][2*h]   - mst[s]);
                        float p1 = __expf(S[mf][nf][2*h+1] - mst[s]);
                        rs[s] += p0 + p1;
                        const int row = (lane >> 2) + 8*h + 16*mf;
                        const int col = 16*wid + 8*nf + 2*(lane & 3);
                        uint32_t lo;
                        uint32_t hi = pack2h(p0, p1, lo);
                        *reinterpret_cast<uint32_t*>(attn_smc + A_PH + swzP(row, col)) = hi;
                        *reinterpret_cast<uint32_t*>(attn_smc + A_PL + swzP(row, col)) = lo;
                    }
#pragma unroll
            for (int s = 0; s < 4; s++) {
                float v = rs[s];
                v += __shfl_xor_sync(0xffffffff, v, 1);
                v += __shfl_xor_sync(0xffffffff, v, 2);
                rs[s] = v;
            }
            if ((lane & 3) == 0) {
#pragma unroll
                for (int s = 0; s < 4; s++) {
                    const int row = (lane >> 2) + 8*(s & 1) + 16*(s >> 1);
                    sums[row*4 + wid] = rs[s];
                }
            }
            __syncthreads();

#pragma unroll
            for (int s = 0; s < 4; s++) {
                const int row = (lane >> 2) + 8*(s & 1) + 16*(s >> 1);
                float4 sp = *reinterpret_cast<float4*>(&sums[row*4]);
                lst[s] = lst[s]*corr[s] + (sp.x + sp.y) + (sp.z + sp.w);
            }
            // rescale O
#pragma unroll
            for (int mf = 0; mf < 2; mf++)
#pragma unroll
                for (int nf = 0; nf < 4; nf++)
#pragma unroll
                    for (int q = 0; q < 4; q++)
                        O[mf][nf][q] *= corr[mf*2 + (q >> 1)];

            // ---- O += Ph*Vh + Ph*Vl + Pl*Vh ----
#pragma unroll
            for (int kc = 0; kc < 4; kc++) {
                uint32_t ph0[4], ph1[4], pl0[4], pl1[4];
                const uint32_t pa0 = swzP(aRow,      kc*16 + aCol);
                const uint32_t pa1 = swzP(16 + aRow, kc*16 + aCol);
                ldmx4(ph0, sb + A_PH + pa0);
                ldmx4(ph1, sb + A_PH + pa1);
                ldmx4(pl0, sb + A_PL + pa0);
                ldmx4(pl1, sb + A_PL + pa1);
                uint32_t vbh[4][2], vbl[4][2];
#pragma unroll
                for (int j = 0; j < 2; j++) {
                    const int key = kc*16 + (lane & 15);
                    const int dcol = 32*wid + 16*j + ((lane & 16) >> 1);
                    uint32_t r[4];
                    const uint32_t va = swz(key, dcol);
                    ldmx4t(r, vBufH + va);
                    vbh[2*j][0]=r[0]; vbh[2*j][1]=r[1]; vbh[2*j+1][0]=r[2]; vbh[2*j+1][1]=r[3];
                    ldmx4t(r, vBufL + va);
                    vbl[2*j][0]=r[0]; vbl[2*j][1]=r[1]; vbl[2*j+1][0]=r[2]; vbl[2*j+1][1]=r[3];
                }
#pragma unroll
                for (int nf = 0; nf < 4; nf++) {
                    mma_bf16(O[0][nf], ph0, vbh[nf]);
                    mma_bf16(O[0][nf], ph0, vbl[nf]);
                    mma_bf16(O[0][nf], pl0, vbh[nf]);
                    mma_bf16(O[1][nf], ph1, vbh[nf]);
                    mma_bf16(O[1][nf], ph1, vbl[nf]);
                    mma_bf16(O[1][nf], pl1, vbh[nf]);
                }
            }
            __syncthreads();
            if (t + 2 < ntiles) issue_kv(sb, buf, tid, Kh, Kl, Vh, Vl, (t + 2) * 64);
            CPCOMMIT();
        }

        // ---- epilogue ----
        float inv[4];
#pragma unroll
        for (int s = 0; s < 4; s++) inv[s] = 1.f / lst[s];
#pragma unroll
        for (int mf = 0; mf < 2; mf++)
#pragma unroll
            for (int nf = 0; nf < 4; nf++)
#pragma unroll
                for (int h = 0; h < 2; h++) {
                    const int s = mf*2 + h;
                    const int row = q0 + (lane >> 2) + 8*h + 16*mf;
                    const int col = 32*wid + 8*nf + 2*(lane & 3);
                    *reinterpret_cast<float2*>(&out[((size_t)(b*TT + row))*DD + col]) =
                        make_float2(O[mf][nf][2*h]*inv[s], O[mf][nf][2*h+1]*inv[s]);
                }
    }
}

// ---------------------------------------------------------------------------
extern "C" void kernel_launch(void* const* d_in, const int* in_sizes, int n_in,
                              void* d_out, int out_size)
{
    const float* X  = (const float*)d_in[0];
    const float* wQ = (const float*)d_in[1];
    const float* wK = (const float*)d_in[2];
    const float* wV = (const float*)d_in[3];
    float* out = (float*)d_out;

    cudaFuncSetAttribute(proj_mma_kernel, cudaFuncAttributeMaxDynamicSharedMemorySize,
                         PROJ_SMEM_BYTES);
    cudaFuncSetAttribute(attn_mma_kernel, cudaFuncAttributeMaxDynamicSharedMemorySize,
                         ATTN_SMEM);

    rope_table_kernel<<<(TT * (DD/2) + 255) / 256, 256>>>();
    proj_mma_kernel<<<dim3(M_TOT / 128, 3), 256, PROJ_SMEM_BYTES>>>(X, wQ, wK, wV);
    attn_mma_kernel<<<BB * 32, 128, ATTN_SMEM>>>(out);
}

// round 9
// speedup vs baseline: 5.9376x; 1.1856x over previous
#include <cuda_runtime.h>
#include <cuda_bf16.h>
#include <cstdint>
#include <math.h>
#include <math_constants.h>

#define BB 4
#define TT 2048
#define EE 1024
#define DD 128
#define M_TOT (BB*TT)

// Split bf16 operands (written by proj, read by attention). 2 MB each.
__device__ __nv_bfloat16 g_Qh[M_TOT*DD];
__device__ __nv_bfloat16 g_Ql[M_TOT*DD];
__device__ __nv_bfloat16 g_Kh[M_TOT*DD];
__device__ __nv_bfloat16 g_Kl[M_TOT*DD];
__device__ __nv_bfloat16 g_Vh[M_TOT*DD];
__device__ __nv_bfloat16 g_Vl[M_TOT*DD];
__device__ float2 g_rope[TT*(DD/2)];   // cos/sin table [t][pair]

// ---------------------------------------------------------------------------
// Warp-MMA helpers (sm_80+ baseline PTX — legal on plain sm_100 target)
// ---------------------------------------------------------------------------
__device__ __forceinline__ uint32_t smem_u32(const void* p) {
    uint32_t a;
    asm("{ .reg .u64 t; cvta.to.shared.u64 t, %1; cvt.u32.u64 %0, t; }" : "=r"(a) : "l"(p));
    return a;
}
__device__ __forceinline__ void ldmx4(uint32_t* r, uint32_t addr) {
    asm volatile("ldmatrix.sync.aligned.m8n8.x4.shared.b16 {%0,%1,%2,%3}, [%4];"
        : "=r"(r[0]), "=r"(r[1]), "=r"(r[2]), "=r"(r[3]) : "r"(addr));
}
__device__ __forceinline__ void ldmx4t(uint32_t* r, uint32_t addr) {
    asm volatile("ldmatrix.sync.aligned.m8n8.x4.trans.shared.b16 {%0,%1,%2,%3}, [%4];"
        : "=r"(r[0]), "=r"(r[1]), "=r"(r[2]), "=r"(r[3]) : "r"(addr));
}
__device__ __forceinline__ void mma_bf16(float* c, const uint32_t* a, const uint32_t* b) {
    asm volatile("mma.sync.aligned.m16n8k16.row.col.f32.bf16.bf16.f32 "
        "{%0,%1,%2,%3}, {%4,%5,%6,%7}, {%8,%9}, {%0,%1,%2,%3};"
        : "+f"(c[0]), "+f"(c[1]), "+f"(c[2]), "+f"(c[3])
        : "r"(a[0]), "r"(a[1]), "r"(a[2]), "r"(a[3]), "r"(b[0]), "r"(b[1]));
}
#define CP16(dst, src) \
    asm volatile("cp.async.cg.shared.global [%0], [%1], 16;" :: "r"(dst), "l"(src))
#define CPCOMMIT() asm volatile("cp.async.commit_group;" ::: "memory")
#define CPWAIT1()  asm volatile("cp.async.wait_group 1;" ::: "memory")

__device__ __forceinline__ void split4(float4 v, uint2& hi, uint2& lo) {
    float f[4] = {v.x, v.y, v.z, v.w};
    unsigned short h[4], l[4];
#pragma unroll
    for (int i = 0; i < 4; i++) {
        __nv_bfloat16 bh = __float2bfloat16(f[i]);
        h[i] = __bfloat16_as_ushort(bh);
        float r = f[i] - __bfloat162float(bh);
        l[i] = __bfloat16_as_ushort(__float2bfloat16(r));
    }
    hi.x = (uint32_t)h[0] | ((uint32_t)h[1] << 16);
    hi.y = (uint32_t)h[2] | ((uint32_t)h[3] << 16);
    lo.x = (uint32_t)l[0] | ((uint32_t)l[1] << 16);
    lo.y = (uint32_t)l[2] | ((uint32_t)l[3] << 16);
}
__device__ __forceinline__ uint32_t pack2h(float a, float b, uint32_t& lo) {
    __nv_bfloat16 ah = __float2bfloat16(a), bh = __float2bfloat16(b);
    float ar = a - __bfloat162float(ah), br = b - __bfloat162float(bh);
    lo = (uint32_t)__bfloat16_as_ushort(__float2bfloat16(ar))
       | ((uint32_t)__bfloat16_as_ushort(__float2bfloat16(br)) << 16);
    return (uint32_t)__bfloat16_as_ushort(ah) | ((uint32_t)__bfloat16_as_ushort(bh) << 16);
}

// swizzled byte offset inside a 128-col bf16 tile (256 B rows)
__device__ __forceinline__ uint32_t swz(uint32_t row, uint32_t col) {
    return row*256u + ((((col>>3) ^ (row&7)))<<4) + (col&7)*2u;
}
// swizzled byte offset inside a 64-col bf16 tile (128 B rows)
__device__ __forceinline__ uint32_t swzP(uint32_t row, uint32_t col) {
    return row*128u + ((((col>>3) ^ (row&7)))<<4) + (col&7)*2u;
}

// ---------------------------------------------------------------------------
// RoPE table
// ---------------------------------------------------------------------------
__global__ __launch_bounds__(256)
void rope_table_kernel()
{
    int idx = blockIdx.x * blockDim.x + threadIdx.x;
    if (idx >= TT * (DD/2)) return;
    int i = idx & 63;
    int t = idx >> 6;
    float freq = exp2f(-0.20762050593046777f * (float)i);
    float ang = (float)t * freq;
    float s, c;
    sincosf(ang, &s, &c);
    g_rope[idx] = make_float2(c, s);
}

// ===========================================================================
// Projection via mma.sync bf16 3-term split; RoPE fused; writes split bf16.
// ===========================================================================
#define STR 40
#define TILE_ELEMS (128*STR)
#define STAGE_ELEMS (4*TILE_ELEMS)
#define PROJ_SMEM_BYTES (2*STAGE_ELEMS*2)

extern __shared__ char proj_sm[];

__global__ __launch_bounds__(256)
void proj_mma_kernel(const float* __restrict__ X,
                     const float* __restrict__ wQ,
                     const float* __restrict__ wK,
                     const float* __restrict__ wV)
{
    const int tid  = threadIdx.x;
    const int wid  = tid >> 5;
    const int lane = tid & 31;
    const int m0   = blockIdx.x * 128;
    const int wsel = blockIdx.y;
    const float* W = (wsel == 0) ? wQ : (wsel == 1) ? wK : wV;
    __nv_bfloat16* oh = (wsel == 0) ? g_Qh : (wsel == 1) ? g_Kh : g_Vh;
    __nv_bfloat16* ol = (wsel == 0) ? g_Ql : (wsel == 1) ? g_Kl : g_Vl;

    const int wm = wid >> 1;
    const int wn = wid & 1;

    const uint32_t sbase = smem_u32(proj_sm);
    __nv_bfloat16* sm16 = reinterpret_cast<__nv_bfloat16*>(proj_sm);

    const int lrow  = tid >> 1;
    const int lhalf = tid & 1;

    float4 px[2][4], pw[2][4];
#pragma unroll
    for (int j = 0; j < 4; j++) {
        px[0][j] = *reinterpret_cast<const float4*>(&X[(size_t)(m0 + lrow) * EE + 16*lhalf + 4*j]);
        pw[0][j] = *reinterpret_cast<const float4*>(&W[(size_t)lrow * EE + 16*lhalf + 4*j]);
    }

    float acc[2][8][4];
#pragma unroll
    for (int mf = 0; mf < 2; mf++)
#pragma unroll
        for (int nf = 0; nf < 8; nf++)
#pragma unroll
            for (int q = 0; q < 4; q++) acc[mf][nf][q] = 0.f;

    for (int c = 0; c < 32; c++) {
        const int buf = c & 1;
        __nv_bfloat16* Ah = sm16 + buf * STAGE_ELEMS;
        __nv_bfloat16* Al = Ah + TILE_ELEMS;
        __nv_bfloat16* Bh = Ah + 2*TILE_ELEMS;
        __nv_bfloat16* Bl = Ah + 3*TILE_ELEMS;

#pragma unroll
        for (int j = 0; j < 4; j++) {
            const int col = 16*lhalf + 4*j;
            uint2 hi, lo;
            split4(px[buf][j], hi, lo);
            *reinterpret_cast<uint2*>(&Ah[lrow*STR + col]) = hi;
            *reinterpret_cast<uint2*>(&Al[lrow*STR + col]) = lo;
            split4(pw[buf][j], hi, lo);
            *reinterpret_cast<uint2*>(&Bh[lrow*STR + col]) = hi;
            *reinterpret_cast<uint2*>(&Bl[lrow*STR + col]) = lo;
        }

        if (c + 1 < 32) {
            const int k0 = (c + 1) * 32;
            const int nb = (c + 1) & 1;
#pragma unroll
            for (int j = 0; j < 4; j++) {
                px[nb][j] = *reinterpret_cast<const float4*>(&X[(size_t)(m0 + lrow) * EE + k0 + 16*lhalf + 4*j]);
                pw[nb][j] = *reinterpret_cast<const float4*>(&W[(size_t)lrow * EE + k0 + 16*lhalf + 4*j]);
            }
        }

        __syncthreads();

        const uint32_t stage = sbase + buf * (STAGE_ELEMS * 2);
#pragma unroll
        for (int kb = 0; kb < 32; kb += 16) {
            uint32_t ah[2][4], al[2][4];
#pragma unroll
            for (int mf = 0; mf < 2; mf++) {
                const int row = 32*wm + 16*mf + (lane & 15);
                const int col = kb + 8*(lane >> 4);
                const uint32_t addrA = stage + (uint32_t)(row*STR + col) * 2;
                ldmx4(ah[mf], addrA);
                ldmx4(al[mf], addrA + TILE_ELEMS*2);
            }
            uint32_t bh[8][2], bl[8][2];
#pragma unroll
            for (int nb4 = 0; nb4 < 4; nb4++) {
                const int n   = 64*wn + 16*nb4 + (lane & 7) + ((lane & 16) >> 1);
                const int col = kb + (lane & 8);
                const uint32_t addrB = stage + (uint32_t)(2*TILE_ELEMS + n*STR + col) * 2;
                uint32_t r[4];
                ldmx4(r, addrB);
                bh[2*nb4][0] = r[0]; bh[2*nb4][1] = r[1];
                bh[2*nb4+1][0] = r[2]; bh[2*nb4+1][1] = r[3];
                ldmx4(r, addrB + TILE_ELEMS*2);
                bl[2*nb4][0] = r[0]; bl[2*nb4][1] = r[1];
                bl[2*nb4+1][0] = r[2]; bl[2*nb4+1][1] = r[3];
            }
#pragma unroll
            for (int mf = 0; mf < 2; mf++)
#pragma unroll
                for (int nf = 0; nf < 8; nf++) {
                    mma_bf16(acc[mf][nf], ah[mf], bh[nf]);
                    mma_bf16(acc[mf][nf], ah[mf], bl[nf]);
                    mma_bf16(acc[mf][nf], al[mf], bh[nf]);
                }
        }
        __syncthreads();
    }

    // epilogue: RoPE (Q/K), split, store bf16 h/l
    const bool do_rope = (wsel < 2);
#pragma unroll
    for (int mf = 0; mf < 2; mf++) {
#pragma unroll
        for (int half = 0; half < 2; half++) {
            const int row = m0 + 32*wm + 16*mf + (lane >> 2) + 8*half;
            const int t = row & (TT - 1);
#pragma unroll
            for (int nf = 0; nf < 8; nf++) {
                const int col = 64*wn + 8*nf + 2*(lane & 3);
                float x0 = acc[mf][nf][2*half];
                float x1 = acc[mf][nf][2*half + 1];
                if (do_rope) {
                    float2 cs = g_rope[t * 64 + (col >> 1)];
                    float r0 = x0 * cs.x - x1 * cs.y;
                    float r1 = x0 * cs.y + x1 * cs.x;
                    x0 = r0; x1 = r1;
                }
                uint32_t lo;
                uint32_t hi = pack2h(x0, x1, lo);
                *reinterpret_cast<uint32_t*>(&oh[(size_t)row * DD + col]) = hi;
                *reinterpret_cast<uint32_t*>(&ol[(size_t)row * DD + col]) = lo;
            }
        }
    }
}

// ===========================================================================
// Tensor-core flash attention. BM=32, BN=64, 256 threads = 8 warps.
// Warp (wm, wk): wm splits M 2x16, wk splits keys 4x16 (S) / D 4x32 (PV).
// cp.async double-buffered K/V.
// ===========================================================================
#define A_QH 0
#define A_QL 8192
#define A_K  16384              // + buf*32768 ; +16384 for low part
#define A_V  81920              // + buf*32768 ; +16384 for low part
#define A_PH 147456
#define A_PL 151552
#define A_MAX 155648
#define A_SUM 156160
#define ATTN_SMEM 156672

extern __shared__ char attn_smc[];

__device__ __forceinline__ void issue_kv(uint32_t sb, int buf, int tid,
                                         const __nv_bfloat16* Kh, const __nv_bfloat16* Kl,
                                         const __nv_bfloat16* Vh, const __nv_bfloat16* Vl,
                                         int kbase)
{
    const int row = tid >> 2;            // 0..63
    const int ch0 = (tid & 3) * 4;
    const size_t gb = ((size_t)(kbase + row)) * DD;
    const uint32_t kb = sb + A_K + buf * 32768;
    const uint32_t vb = sb + A_V + buf * 32768;
#pragma unroll
    for (int j = 0; j < 4; j++) {
        const int ch = ch0 + j;
        const uint32_t d = swz(row, ch * 8);
        CP16(kb + d,         Kh + gb + ch*8);
        CP16(kb + 16384 + d, Kl + gb + ch*8);
        CP16(vb + d,         Vh + gb + ch*8);
        CP16(vb + 16384 + d, Vl + gb + ch*8);
    }
}

__global__ __launch_bounds__(256)
void attn_mma_kernel(float* __restrict__ out)
{
    const uint32_t sb = smem_u32(attn_smc);
    const int tid  = threadIdx.x;
    const int wid  = tid >> 5;
    const int lane = tid & 31;
    const int wm   = wid >> 2;           // 0..1: M half (16 rows)
    const int wk   = wid & 3;            // 0..3: key group (S) / D group (PV)
    const int b    = blockIdx.x >> 5;
    const int pb   = blockIdx.x & 31;
    const float scale = 0.08838834764831845f;

    const __nv_bfloat16* Qh = g_Qh + (size_t)b*TT*DD;
    const __nv_bfloat16* Ql = g_Ql + (size_t)b*TT*DD;
    const __nv_bfloat16* Kh = g_Kh + (size_t)b*TT*DD;
    const __nv_bfloat16* Kl = g_Kl + (size_t)b*TT*DD;
    const __nv_bfloat16* Vh = g_Vh + (size_t)b*TT*DD;
    const __nv_bfloat16* Vl = g_Vl + (size_t)b*TT*DD;

    float* maxs = reinterpret_cast<float*>(attn_smc + A_MAX);
    float* sums = reinterpret_cast<float*>(attn_smc + A_SUM);

    for (int sel = 0; sel < 2; sel++) {
        const int q0 = (sel ? (63 - pb) : pb) * 32;
        const int ntiles = q0 / 64 + 1;

        // load Q tile (h/l) into swizzled smem (256 threads)
        {
            const int row = tid >> 3;            // 0..31
            const int cb  = (tid & 7) * 2;
#pragma unroll
            for (int j = 0; j < 2; j++) {
                const int ch = cb + j;
                const size_t gq = ((size_t)(q0 + row)) * DD + ch*8;
                const uint32_t d = swz(row, ch * 8);
                *reinterpret_cast<uint4*>(attn_smc + A_QH + d) =
                    *reinterpret_cast<const uint4*>(Qh + gq);
                *reinterpret_cast<uint4*>(attn_smc + A_QL + d) =
                    *reinterpret_cast<const uint4*>(Ql + gq);
            }
        }
        issue_kv(sb, 0, tid, Kh, Kl, Vh, Vl, 0);
        CPCOMMIT();
        if (ntiles > 1) issue_kv(sb, 1, tid, Kh, Kl, Vh, Vl, 64);
        CPCOMMIT();
        __syncthreads();

        float mst[2], lst[2], O[4][4];
#pragma unroll
        for (int s = 0; s < 2; s++) { mst[s] = -CUDART_INF_F; lst[s] = 0.f; }
#pragma unroll
        for (int nf = 0; nf < 4; nf++)
#pragma unroll
            for (int q = 0; q < 4; q++) O[nf][q] = 0.f;

        for (int t = 0; t < ntiles; t++) {
            const int buf = t & 1;
            const int kbase = t * 64;
            const uint32_t kBufH = sb + A_K + buf*32768;
            const uint32_t kBufL = kBufH + 16384;
            const uint32_t vBufH = sb + A_V + buf*32768;
            const uint32_t vBufL = vBufH + 16384;

            CPWAIT1();
            __syncthreads();

            // ---- S = Qh*Kh + Qh*Kl + Ql*Kh  (warp: rows 16*wm, keys 16*wk) ----
            float S[2][4];
#pragma unroll
            for (int nf = 0; nf < 2; nf++)
#pragma unroll
                for (int q = 0; q < 4; q++) S[nf][q] = 0.f;

            const int aRow = 16*wm + (lane & 15);
            const int aCol = 8 * (lane >> 4);
            const int bRow = 16*wk + (lane & 7) + ((lane & 16) >> 1);
            const int bCol = lane & 8;
#pragma unroll
            for (int kc = 0; kc < 8; kc++) {
                uint32_t qh[4], ql[4];
                const uint32_t a = swz(aRow, kc*16 + aCol);
                ldmx4(qh, sb + A_QH + a);
                ldmx4(ql, sb + A_QL + a);
                uint32_t rb[4], kbh[2][2], kbl[2][2];
                const uint32_t ba = swz(bRow, kc*16 + bCol);
                ldmx4(rb, kBufH + ba);
                kbh[0][0]=rb[0]; kbh[0][1]=rb[1]; kbh[1][0]=rb[2]; kbh[1][1]=rb[3];
                ldmx4(rb, kBufL + ba);
                kbl[0][0]=rb[0]; kbl[0][1]=rb[1]; kbl[1][0]=rb[2]; kbl[1][1]=rb[3];
#pragma unroll
                for (int nf = 0; nf < 2; nf++) {
                    mma_bf16(S[nf], qh, kbh[nf]);
                    mma_bf16(S[nf], qh, kbl[nf]);
                    mma_bf16(S[nf], ql, kbh[nf]);
                }
            }

            // ---- mask + scale ----
            const bool lastt = (t == ntiles - 1);
#pragma unroll
            for (int nf = 0; nf < 2; nf++)
#pragma unroll
                for (int q = 0; q < 4; q++) {
                    const int gcol = kbase + 16*wk + 8*nf + 2*(lane & 3) + (q & 1);
                    const int grow = q0 + 16*wm + (lane >> 2) + 8*(q >> 1);
                    if (lastt && gcol > grow) S[nf][q] = -1e30f;
                    else S[nf][q] *= scale;
                }

            // ---- partial row max -> smem ----
#pragma unroll
            for (int h = 0; h < 2; h++) {
                float v = fmaxf(fmaxf(S[0][2*h], S[0][2*h+1]),
                                fmaxf(S[1][2*h], S[1][2*h+1]));
                v = fmaxf(v, __shfl_xor_sync(0xffffffff, v, 1));
                v = fmaxf(v, __shfl_xor_sync(0xffffffff, v, 2));
                if ((lane & 3) == 0)
                    maxs[(16*wm + (lane >> 2) + 8*h)*4 + wk] = v;
            }
            __syncthreads();

            // ---- global max, p=exp, write P, partial sums ----
            float corr[2], rs[2];
#pragma unroll
            for (int h = 0; h < 2; h++) {
                const int row = 16*wm + (lane >> 2) + 8*h;
                float4 mp = *reinterpret_cast<float4*>(&maxs[row*4]);
                float mn = fmaxf(fmaxf(mp.x, mp.y), fmaxf(mp.z, mp.w));
                float mnew = fmaxf(mst[h], mn);
                corr[h] = __expf(mst[h] - mnew);
                mst[h] = mnew;
                rs[h] = 0.f;
            }
#pragma unroll
            for (int nf = 0; nf < 2; nf++)
#pragma unroll
                for (int h = 0; h < 2; h++) {
                    float p0 = __expf(S[nf][2*h]   - mst[h]);
                    float p1 = __expf(S[nf][2*h+1] - mst[h]);
                    rs[h] += p0 + p1;
                    const int row = 16*wm + (lane >> 2) + 8*h;
                    const int col = 16*wk + 8*nf + 2*(lane & 3);
                    uint32_t lo;
                    uint32_t hi = pack2h(p0, p1, lo);
                    *reinterpret_cast<uint32_t*>(attn_smc + A_PH + swzP(row, col)) = hi;
                    *reinterpret_cast<uint32_t*>(attn_smc + A_PL + swzP(row, col)) = lo;
                }
#pragma unroll
            for (int h = 0; h < 2; h++) {
                float v = rs[h];
                v += __shfl_xor_sync(0xffffffff, v, 1);
                v += __shfl_xor_sync(0xffffffff, v, 2);
                if ((lane & 3) == 0)
                    sums[(16*wm + (lane >> 2) + 8*h)*4 + wk] = v;
            }
            __syncthreads();

#pragma unroll
            for (int h = 0; h < 2; h++) {
                const int row = 16*wm + (lane >> 2) + 8*h;
                float4 sp = *reinterpret_cast<float4*>(&sums[row*4]);
                lst[h] = lst[h]*corr[h] + (sp.x + sp.y) + (sp.z + sp.w);
            }
            // rescale O
#pragma unroll
            for (int nf = 0; nf < 4; nf++)
#pragma unroll
                for (int q = 0; q < 4; q++)
                    O[nf][q] *= corr[q >> 1];

            // ---- O += Ph*Vh + Ph*Vl + Pl*Vh  (warp: rows 16*wm, D cols 32*wk) ----
#pragma unroll
            for (int kc = 0; kc < 4; kc++) {
                uint32_t ph[4], pl[4];
                const uint32_t pa = swzP(16*wm + (lane & 15), kc*16 + 8*(lane >> 4));
                ldmx4(ph, sb + A_PH + pa);
                ldmx4(pl, sb + A_PL + pa);
                uint32_t vbh[4][2], vbl[4][2];
#pragma unroll
                for (int j = 0; j < 2; j++) {
                    const int key = kc*16 + (lane & 15);
                    const int dcol = 32*wk + 16*j + ((lane & 16) >> 1);
                    uint32_t r[4];
                    const uint32_t va = swz(key, dcol);
                    ldmx4t(r, vBufH + va);
                    vbh[2*j][0]=r[0]; vbh[2*j][1]=r[1]; vbh[2*j+1][0]=r[2]; vbh[2*j+1][1]=r[3];
                    ldmx4t(r, vBufL + va);
                    vbl[2*j][0]=r[0]; vbl[2*j][1]=r[1]; vbl[2*j+1][0]=r[2]; vbl[2*j+1][1]=r[3];
                }
#pragma unroll
                for (int nf = 0; nf < 4; nf++) {
                    mma_bf16(O[nf], ph, vbh[nf]);
                    mma_bf16(O[nf], ph, vbl[nf]);
                    mma_bf16(O[nf], pl, vbh[nf]);
                }
            }
            __syncthreads();
            if (t + 2 < ntiles) issue_kv(sb, buf, tid, Kh, Kl, Vh, Vl, (t + 2) * 64);
            CPCOMMIT();
        }

        // ---- epilogue ----
        float inv[2];
#pragma unroll
        for (int h = 0; h < 2; h++) inv[h] = 1.f / lst[h];
#pragma unroll
        for (int nf = 0; nf < 4; nf++)
#pragma unroll
            for (int h = 0; h < 2; h++) {
                const int row = q0 + 16*wm + (lane >> 2) + 8*h;
                const int col = 32*wk + 8*nf + 2*(lane & 3);
                *reinterpret_cast<float2*>(&out[((size_t)(b*TT + row))*DD + col]) =
                    make_float2(O[nf][2*h]*inv[h], O[nf][2*h+1]*inv[h]);
            }
    }
}

// ---------------------------------------------------------------------------
extern "C" void kernel_launch(void* const* d_in, const int* in_sizes, int n_in,
                              void* d_out, int out_size)
{
    const float* X  = (const float*)d_in[0];
    const float* wQ = (const float*)d_in[1];
    const float* wK = (const float*)d_in[2];
    const float* wV = (const float*)d_in[3];
    float* out = (float*)d_out;

    cudaFuncSetAttribute(proj_mma_kernel, cudaFuncAttributeMaxDynamicSharedMemorySize,
                         PROJ_SMEM_BYTES);
    cudaFuncSetAttribute(attn_mma_kernel, cudaFuncAttributeMaxDynamicSharedMemorySize,
                         ATTN_SMEM);

    rope_table_kernel<<<(TT * (DD/2) + 255) / 256, 256>>>();
    proj_mma_kernel<<<dim3(M_TOT / 128, 3), 256, PROJ_SMEM_BYTES>>>(X, wQ, wK, wV);
    attn_mma_kernel<<<BB * 32, 256, ATTN_SMEM>>>(out);
}

// round 11
// speedup vs baseline: 6.1598x; 1.0374x over previous
#include <cuda_runtime.h>
#include <cuda_bf16.h>
#include <cstdint>
#include <math.h>
#include <math_constants.h>

#define BB 4
#define TT 2048
#define EE 1024
#define DD 128
#define M_TOT (BB*TT)
#define SCALE 0.08838834764831845f

// Split bf16 operands (written by proj, read by attention). 2 MB each.
__device__ __nv_bfloat16 g_Qh[M_TOT*DD];
__device__ __nv_bfloat16 g_Ql[M_TOT*DD];
__device__ __nv_bfloat16 g_Kh[M_TOT*DD];
__device__ __nv_bfloat16 g_Kl[M_TOT*DD];
__device__ __nv_bfloat16 g_Vh[M_TOT*DD];
__device__ __nv_bfloat16 g_Vl[M_TOT*DD];
__device__ float2 g_rope[TT*(DD/2)];   // cos/sin table [t][pair]

// ---------------------------------------------------------------------------
// Warp-MMA helpers (sm_80+ baseline PTX — legal on plain sm_100 target)
// ---------------------------------------------------------------------------
__device__ __forceinline__ uint32_t smem_u32(const void* p) {
    uint32_t a;
    asm("{ .reg .u64 t; cvta.to.shared.u64 t, %1; cvt.u32.u64 %0, t; }" : "=r"(a) : "l"(p));
    return a;
}
__device__ __forceinline__ void ldmx4(uint32_t* r, uint32_t addr) {
    asm volatile("ldmatrix.sync.aligned.m8n8.x4.shared.b16 {%0,%1,%2,%3}, [%4];"
        : "=r"(r[0]), "=r"(r[1]), "=r"(r[2]), "=r"(r[3]) : "r"(addr));
}
__device__ __forceinline__ void ldmx4t(uint32_t* r, uint32_t addr) {
    asm volatile("ldmatrix.sync.aligned.m8n8.x4.trans.shared.b16 {%0,%1,%2,%3}, [%4];"
        : "=r"(r[0]), "=r"(r[1]), "=r"(r[2]), "=r"(r[3]) : "r"(addr));
}
__device__ __forceinline__ void mma_bf16(float* c, const uint32_t* a, const uint32_t* b) {
    asm volatile("mma.sync.aligned.m16n8k16.row.col.f32.bf16.bf16.f32 "
        "{%0,%1,%2,%3}, {%4,%5,%6,%7}, {%8,%9}, {%0,%1,%2,%3};"
        : "+f"(c[0]), "+f"(c[1]), "+f"(c[2]), "+f"(c[3])
        : "r"(a[0]), "r"(a[1]), "r"(a[2]), "r"(a[3]), "r"(b[0]), "r"(b[1]));
}
#define CP16(dst, src) \
    asm volatile("cp.async.cg.shared.global [%0], [%1], 16;" :: "r"(dst), "l"(src))
#define CPCOMMIT() asm volatile("cp.async.commit_group;" ::: "memory")
#define CPWAIT1()  asm volatile("cp.async.wait_group 1;" ::: "memory")
#define HALFBAR(id) asm volatile("bar.sync %0, 128;" :: "r"(id) : "memory")

__device__ __forceinline__ void split4(float4 v, uint2& hi, uint2& lo) {
    float f[4] = {v.x, v.y, v.z, v.w};
    unsigned short h[4], l[4];
#pragma unroll
    for (int i = 0; i < 4; i++) {
        __nv_bfloat16 bh = __float2bfloat16(f[i]);
        h[i] = __bfloat16_as_ushort(bh);
        float r = f[i] - __bfloat162float(bh);
        l[i] = __bfloat16_as_ushort(__float2bfloat16(r));
    }
    hi.x = (uint32_t)h[0] | ((uint32_t)h[1] << 16);
    hi.y = (uint32_t)h[2] | ((uint32_t)h[3] << 16);
    lo.x = (uint32_t)l[0] | ((uint32_t)l[1] << 16);
    lo.y = (uint32_t)l[2] | ((uint32_t)l[3] << 16);
}
__device__ __forceinline__ uint32_t pack2h(float a, float b, uint32_t& lo) {
    __nv_bfloat16 ah = __float2bfloat16(a), bh = __float2bfloat16(b);
    float ar = a - __bfloat162float(ah), br = b - __bfloat162float(bh);
    lo = (uint32_t)__bfloat16_as_ushort(__float2bfloat16(ar))
       | ((uint32_t)__bfloat16_as_ushort(__float2bfloat16(br)) << 16);
    return (uint32_t)__bfloat16_as_ushort(ah) | ((uint32_t)__bfloat16_as_ushort(bh) << 16);
}

// swizzled byte offset inside a 128-col bf16 tile (256 B rows)
__device__ __forceinline__ uint32_t swz(uint32_t row, uint32_t col) {
    return row*256u + ((((col>>3) ^ (row&7)))<<4) + (col&7)*2u;
}
// swizzled byte offset inside a 64-col bf16 tile (128 B rows)
__device__ __forceinline__ uint32_t swzP(uint32_t row, uint32_t col) {
    return row*128u + ((((col>>3) ^ (row&7)))<<4) + (col&7)*2u;
}

// ---------------------------------------------------------------------------
// RoPE table
// ---------------------------------------------------------------------------
__global__ __launch_bounds__(256)
void rope_table_kernel()
{
    int idx = blockIdx.x * blockDim.x + threadIdx.x;
    if (idx >= TT * (DD/2)) return;
    int i = idx & 63;
    int t = idx >> 6;
    float freq = exp2f(-0.20762050593046777f * (float)i);
    float ang = (float)t * freq;
    float s, c;
    sincosf(ang, &s, &c);
    g_rope[idx] = make_float2(c, s);
}

// ===========================================================================
// Projection via mma.sync bf16 3-term split; RoPE fused; writes split bf16.
// Q additionally pre-scaled by 1/sqrt(d) (folded out of attention).
// ===========================================================================
#define STR 40
#define TILE_ELEMS (128*STR)
#define STAGE_ELEMS (4*TILE_ELEMS)
#define PROJ_SMEM_BYTES (2*STAGE_ELEMS*2)

extern __shared__ char proj_sm[];

__global__ __launch_bounds__(256)
void proj_mma_kernel(const float* __restrict__ X,
                     const float* __restrict__ wQ,
                     const float* __restrict__ wK,
                     const float* __restrict__ wV)
{
    const int tid  = threadIdx.x;
    const int wid  = tid >> 5;
    const int lane = tid & 31;
    const int m0   = blockIdx.x * 128;
    const int wsel = blockIdx.y;
    const float* W = (wsel == 0) ? wQ : (wsel == 1) ? wK : wV;
    __nv_bfloat16* oh = (wsel == 0) ? g_Qh : (wsel == 1) ? g_Kh : g_Vh;
    __nv_bfloat16* ol = (wsel == 0) ? g_Ql : (wsel == 1) ? g_Kl : g_Vl;

    const int wm = wid >> 1;
    const int wn = wid & 1;

    const uint32_t sbase = smem_u32(proj_sm);
    __nv_bfloat16* sm16 = reinterpret_cast<__nv_bfloat16*>(proj_sm);

    const int lrow  = tid >> 1;
    const int lhalf = tid & 1;

    float4 px[2][4], pw[2][4];
#pragma unroll
    for (int j = 0; j < 4; j++) {
        px[0][j] = *reinterpret_cast<const float4*>(&X[(size_t)(m0 + lrow) * EE + 16*lhalf + 4*j]);
        pw[0][j] = *reinterpret_cast<const float4*>(&W[(size_t)lrow * EE + 16*lhalf + 4*j]);
    }

    float acc[2][8][4];
#pragma unroll
    for (int mf = 0; mf < 2; mf++)
#pragma unroll
        for (int nf = 0; nf < 8; nf++)
#pragma unroll
            for (int q = 0; q < 4; q++) acc[mf][nf][q] = 0.f;

    for (int c = 0; c < 32; c++) {
        const int buf = c & 1;
        __nv_bfloat16* Ah = sm16 + buf * STAGE_ELEMS;
        __nv_bfloat16* Al = Ah + TILE_ELEMS;
        __nv_bfloat16* Bh = Ah + 2*TILE_ELEMS;
        __nv_bfloat16* Bl = Ah + 3*TILE_ELEMS;

#pragma unroll
        for (int j = 0; j < 4; j++) {
            const int col = 16*lhalf + 4*j;
            uint2 hi, lo;
            split4(px[buf][j], hi, lo);
            *reinterpret_cast<uint2*>(&Ah[lrow*STR + col]) = hi;
            *reinterpret_cast<uint2*>(&Al[lrow*STR + col]) = lo;
            split4(pw[buf][j], hi, lo);
            *reinterpret_cast<uint2*>(&Bh[lrow*STR + col]) = hi;
            *reinterpret_cast<uint2*>(&Bl[lrow*STR + col]) = lo;
        }

        if (c + 1 < 32) {
            const int k0 = (c + 1) * 32;
            const int nb = (c + 1) & 1;
#pragma unroll
            for (int j = 0; j < 4; j++) {
                px[nb][j] = *reinterpret_cast<const float4*>(&X[(size_t)(m0 + lrow) * EE + k0 + 16*lhalf + 4*j]);
                pw[nb][j] = *reinterpret_cast<const float4*>(&W[(size_t)lrow * EE + k0 + 16*lhalf + 4*j]);
            }
        }

        __syncthreads();

        const uint32_t stage = sbase + buf * (STAGE_ELEMS * 2);
#pragma unroll
        for (int kb = 0; kb < 32; kb += 16) {
            uint32_t ah[2][4], al[2][4];
#pragma unroll
            for (int mf = 0; mf < 2; mf++) {
                const int row = 32*wm + 16*mf + (lane & 15);
                const int col = kb + 8*(lane >> 4);
                const uint32_t addrA = stage + (uint32_t)(row*STR + col) * 2;
                ldmx4(ah[mf], addrA);
                ldmx4(al[mf], addrA + TILE_ELEMS*2);
            }
            uint32_t bh[8][2], bl[8][2];
#pragma unroll
            for (int nb4 = 0; nb4 < 4; nb4++) {
                const int n   = 64*wn + 16*nb4 + (lane & 7) + ((lane & 16) >> 1);
                const int col = kb + (lane & 8);
                const uint32_t addrB = stage + (uint32_t)(2*TILE_ELEMS + n*STR + col) * 2;
                uint32_t r[4];
                ldmx4(r, addrB);
                bh[2*nb4][0] = r[0]; bh[2*nb4][1] = r[1];
                bh[2*nb4+1][0] = r[2]; bh[2*nb4+1][1] = r[3];
                ldmx4(r, addrB + TILE_ELEMS*2);
                bl[2*nb4][0] = r[0]; bl[2*nb4][1] = r[1];
                bl[2*nb4+1][0] = r[2]; bl[2*nb4+1][1] = r[3];
            }
#pragma unroll
            for (int mf = 0; mf < 2; mf++)
#pragma unroll
                for (int nf = 0; nf < 8; nf++) {
                    mma_bf16(acc[mf][nf], ah[mf], bh[nf]);
                    mma_bf16(acc[mf][nf], ah[mf], bl[nf]);
                    mma_bf16(acc[mf][nf], al[mf], bh[nf]);
                }
        }
        __syncthreads();
    }

    // epilogue: RoPE (Q/K), Q pre-scale, split, store bf16 h/l
    const bool do_rope = (wsel < 2);
    const bool do_scale = (wsel == 0);
#pragma unroll
    for (int mf = 0; mf < 2; mf++) {
#pragma unroll
        for (int half = 0; half < 2; half++) {
            const int row = m0 + 32*wm + 16*mf + (lane >> 2) + 8*half;
            const int t = row & (TT - 1);
#pragma unroll
            for (int nf = 0; nf < 8; nf++) {
                const int col = 64*wn + 8*nf + 2*(lane & 3);
                float x0 = acc[mf][nf][2*half];
                float x1 = acc[mf][nf][2*half + 1];
                if (do_rope) {
                    float2 cs = g_rope[t * 64 + (col >> 1)];
                    float r0 = x0 * cs.x - x1 * cs.y;
                    float r1 = x0 * cs.y + x1 * cs.x;
                    x0 = r0; x1 = r1;
                }
                if (do_scale) { x0 *= SCALE; x1 *= SCALE; }
                uint32_t lo;
                uint32_t hi = pack2h(x0, x1, lo);
                *reinterpret_cast<uint32_t*>(&oh[(size_t)row * DD + col]) = hi;
                *reinterpret_cast<uint32_t*>(&ol[(size_t)row * DD + col]) = lo;
            }
        }
    }
}

// ===========================================================================
// Tensor-core flash attention, unnormalized-exp formulation.
// BM=32, BN=64, 256 threads = 8 warps; warp (wm, wk).
// Q frags register-resident; P area aliases Q staging area.
// No running max: p = exp(s) (Q pre-scaled); row sums in registers;
// single normalization at q-tile end. Half-barrier before PV.
// ===========================================================================
#define A_PH 0                 // P hi / Q hi staging (8 KB)
#define A_PL 8192              // P lo / Q lo staging (8 KB)
#define A_K  16384             // K h/l double buf (2 x 32 KB)
#define A_V  81920             // V h/l double buf (2 x 32 KB)
#define A_SUM 147456           // 512 B
#define ATTN_SMEM 147968

extern __shared__ char attn_smc[];

__device__ __forceinline__ void issue_kv(uint32_t sb, int buf, int tid,
                                         const __nv_bfloat16* Kh, const __nv_bfloat16* Kl,
                                         const __nv_bfloat16* Vh, const __nv_bfloat16* Vl,
                                         int kbase)
{
    const int row = tid >> 2;            // 0..63
    const int ch0 = (tid & 3) * 4;
    const size_t gb = ((size_t)(kbase + row)) * DD;
    const uint32_t kb = sb + A_K + buf * 32768;
    const uint32_t vb = sb + A_V + buf * 32768;
#pragma unroll
    for (int j = 0; j < 4; j++) {
        const int ch = ch0 + j;
        const uint32_t d = swz(row, ch * 8);
        CP16(kb + d,         Kh + gb + ch*8);
        CP16(kb + 16384 + d, Kl + gb + ch*8);
        CP16(vb + d,         Vh + gb + ch*8);
        CP16(vb + 16384 + d, Vl + gb + ch*8);
    }
}

__global__ __launch_bounds__(256)
void attn_mma_kernel(float* __restrict__ out)
{
    const uint32_t sb = smem_u32(attn_smc);
    const int tid  = threadIdx.x;
    const int wid  = tid >> 5;
    const int lane = tid & 31;
    const int wm   = wid >> 2;           // 0..1: M half (16 rows)
    const int wk   = wid & 3;            // 0..3: key group (S) / D group (PV)
    const int b    = blockIdx.x >> 5;
    const int pb   = blockIdx.x & 31;

    const __nv_bfloat16* Qh = g_Qh + (size_t)b*TT*DD;
    const __nv_bfloat16* Ql = g_Ql + (size_t)b*TT*DD;
    const __nv_bfloat16* Kh = g_Kh + (size_t)b*TT*DD;
    const __nv_bfloat16* Kl = g_Kl + (size_t)b*TT*DD;
    const __nv_bfloat16* Vh = g_Vh + (size_t)b*TT*DD;
    const __nv_bfloat16* Vl = g_Vl + (size_t)b*TT*DD;

    float* sums = reinterpret_cast<float*>(attn_smc + A_SUM);

    for (int sel = 0; sel < 2; sel++) {
        const int q0 = (sel ? (63 - pb) : pb) * 32;
        const int ntiles = q0 / 64 + 1;

        // stage Q tile (h/l) into P area (swizzled, 128-col layout)
        {
            const int row = tid >> 3;            // 0..31
            const int cb  = (tid & 7) * 2;
#pragma unroll
            for (int j = 0; j < 2; j++) {
                const int ch = cb + j;
                const size_t gq = ((size_t)(q0 + row)) * DD + ch*8;
                const uint32_t d = swz(row, ch * 8);
                *reinterpret_cast<uint4*>(attn_smc + A_PH + d) =
                    *reinterpret_cast<const uint4*>(Qh + gq);
                *reinterpret_cast<uint4*>(attn_smc + A_PL + d) =
                    *reinterpret_cast<const uint4*>(Ql + gq);
            }
        }
        issue_kv(sb, 0, tid, Kh, Kl, Vh, Vl, 0);
        CPCOMMIT();
        if (ntiles > 1) issue_kv(sb, 1, tid, Kh, Kl, Vh, Vl, 64);
        CPCOMMIT();
        __syncthreads();

        // hoist Q fragments into registers (whole K-dim, h+l)
        uint32_t qfh[8][4], qfl[8][4];
        {
            const int aRow = 16*wm + (lane & 15);
            const int aCol = 8 * (lane >> 4);
#pragma unroll
            for (int kc = 0; kc < 8; kc++) {
                const uint32_t a = swz(aRow, kc*16 + aCol);
                ldmx4(qfh[kc], sb + A_PH + a);
                ldmx4(qfl[kc], sb + A_PL + a);
            }
        }

        float lsum[2] = {0.f, 0.f};
        float O[4][4];
#pragma unroll
        for (int nf = 0; nf < 4; nf++)
#pragma unroll
            for (int q = 0; q < 4; q++) O[nf][q] = 0.f;

        for (int t = 0; t < ntiles; t++) {
            const int buf = t & 1;
            const int kbase = t * 64;
            const uint32_t kBufH = sb + A_K + buf*32768;
            const uint32_t kBufL = kBufH + 16384;
            const uint32_t vBufH = sb + A_V + buf*32768;
            const uint32_t vBufL = vBufH + 16384;

            CPWAIT1();
            __syncthreads();

            // ---- S = Qh*Kh + Qh*Kl + Ql*Kh (Q from regs) ----
            float S[2][4];
#pragma unroll
            for (int nf = 0; nf < 2; nf++)
#pragma unroll
                for (int q = 0; q < 4; q++) S[nf][q] = 0.f;

            const int bRow = 16*wk + (lane & 7) + ((lane & 16) >> 1);
            const int bCol = lane & 8;
#pragma unroll
            for (int kc = 0; kc < 8; kc++) {
                uint32_t rb[4], kbh[2][2], kbl[2][2];
                const uint32_t ba = swz(bRow, kc*16 + bCol);
                ldmx4(rb, kBufH + ba);
                kbh[0][0]=rb[0]; kbh[0][1]=rb[1]; kbh[1][0]=rb[2]; kbh[1][1]=rb[3];
                ldmx4(rb, kBufL + ba);
                kbl[0][0]=rb[0]; kbl[0][1]=rb[1]; kbl[1][0]=rb[2]; kbl[1][1]=rb[3];
#pragma unroll
                for (int nf = 0; nf < 2; nf++) {
                    mma_bf16(S[nf], qfh[kc], kbh[nf]);
                    mma_bf16(S[nf], qfh[kc], kbl[nf]);
                    mma_bf16(S[nf], qfl[kc], kbh[nf]);
                }
            }

            // ---- p = exp(s) (masked -> 0), local row sums, write P h/l ----
            const bool lastt = (t == ntiles - 1);
#pragma unroll
            for (int nf = 0; nf < 2; nf++)
#pragma unroll
                for (int h = 0; h < 2; h++) {
                    const int gcol0 = kbase + 16*wk + 8*nf + 2*(lane & 3);
                    const int grow  = q0 + 16*wm + (lane >> 2) + 8*h;
                    float p0 = (lastt && gcol0     > grow) ? 0.f : __expf(S[nf][2*h]);
                    float p1 = (lastt && gcol0 + 1 > grow) ? 0.f : __expf(S[nf][2*h+1]);
                    lsum[h] += p0 + p1;
                    const int row = 16*wm + (lane >> 2) + 8*h;
                    const int col = 16*wk + 8*nf + 2*(lane & 3);
                    uint32_t lo;
                    uint32_t hi = pack2h(p0, p1, lo);
                    *reinterpret_cast<uint32_t*>(attn_smc + A_PH + swzP(row, col)) = hi;
                    *reinterpret_cast<uint32_t*>(attn_smc + A_PL + swzP(row, col)) = lo;
                }
            HALFBAR(1 + wm);   // P rows are wm-half private

            // ---- O += Ph*Vh + Ph*Vl + Pl*Vh ----
#pragma unroll
            for (int kc = 0; kc < 4; kc++) {
                uint32_t ph[4], pl[4];
                const uint32_t pa = swzP(16*wm + (lane & 15), kc*16 + 8*(lane >> 4));
                ldmx4(ph, sb + A_PH + pa);
                ldmx4(pl, sb + A_PL + pa);
                uint32_t vbh[4][2], vbl[4][2];
#pragma unroll
                for (int j = 0; j < 2; j++) {
                    const int key = kc*16 + (lane & 15);
                    const int dcol = 32*wk + 16*j + ((lane & 16) >> 1);
                    uint32_t r[4];
                    const uint32_t va = swz(key, dcol);
                    ldmx4t(r, vBufH + va);
                    vbh[2*j][0]=r[0]; vbh[2*j][1]=r[1]; vbh[2*j+1][0]=r[2]; vbh[2*j+1][1]=r[3];
                    ldmx4t(r, vBufL + va);
                    vbl[2*j][0]=r[0]; vbl[2*j][1]=r[1]; vbl[2*j+1][0]=r[2]; vbl[2*j+1][1]=r[3];
                }
#pragma unroll
                for (int nf = 0; nf < 4; nf++) {
                    mma_bf16(O[nf], ph, vbh[nf]);
                    mma_bf16(O[nf], ph, vbl[nf]);
                    mma_bf16(O[nf], pl, vbh[nf]);
                }
            }
            __syncthreads();
            if (t + 2 < ntiles) issue_kv(sb, buf, tid, Kh, Kl, Vh, Vl, (t + 2) * 64);
            CPCOMMIT();
        }

        // ---- final row-sum reduction (once per q-tile) + normalize ----
#pragma unroll
        for (int h = 0; h < 2; h++) {
            float v = lsum[h];
            v += __shfl_xor_sync(0xffffffff, v, 1);
            v += __shfl_xor_sync(0xffffffff, v, 2);
            if ((lane & 3) == 0)
                sums[(16*wm + (lane >> 2) + 8*h)*4 + wk] = v;
        }
        __syncthreads();
        float inv[2];
#pragma unroll
        for (int h = 0; h < 2; h++) {
            const int row = 16*wm + (lane >> 2) + 8*h;
            float4 sp = *reinterpret_cast<float4*>(&sums[row*4]);
            inv[h] = 1.f / ((sp.x + sp.y) + (sp.z + sp.w));
        }
#pragma unroll
        for (int nf = 0; nf < 4; nf++)
#pragma unroll
            for (int h = 0; h < 2; h++) {
                const int row = q0 + 16*wm + (lane >> 2) + 8*h;
                const int col = 32*wk + 8*nf + 2*(lane & 3);
                *reinterpret_cast<float2*>(&out[((size_t)(b*TT + row))*DD + col]) =
                    make_float2(O[nf][2*h]*inv[h], O[nf][2*h+1]*inv[h]);
            }
        __syncthreads();
    }
}

// ---------------------------------------------------------------------------
extern "C" void kernel_launch(void* const* d_in, const int* in_sizes, int n_in,
                              void* d_out, int out_size)
{
    const float* X  = (const float*)d_in[0];
    const float* wQ = (const float*)d_in[1];
    const float* wK = (const float*)d_in[2];
    const float* wV = (const float*)d_in[3];
    float* out = (float*)d_out;

    cudaFuncSetAttribute(proj_mma_kernel, cudaFuncAttributeMaxDynamicSharedMemorySize,
                         PROJ_SMEM_BYTES);
    cudaFuncSetAttribute(attn_mma_kernel, cudaFuncAttributeMaxDynamicSharedMemorySize,
                         ATTN_SMEM);

    rope_table_kernel<<<(TT * (DD/2) + 255) / 256, 256>>>();
    proj_mma_kernel<<<dim3(M_TOT / 128, 3), 256, PROJ_SMEM_BYTES>>>(X, wQ, wK, wV);
    attn_mma_kernel<<<BB * 32, 256, ATTN_SMEM>>>(out);
}

// round 12
// speedup vs baseline: 6.2195x; 1.0097x over previous
#include <cuda_runtime.h>
#include <cuda_bf16.h>
#include <cstdint>
#include <math.h>
#include <math_constants.h>

#define BB 4
#define TT 2048
#define EE 1024
#define DD 128
#define M_TOT (BB*TT)
#define SCALE 0.08838834764831845f

// Split bf16 operands (written by proj, read by attention). 2 MB each.
__device__ __nv_bfloat16 g_Qh[M_TOT*DD];
__device__ __nv_bfloat16 g_Ql[M_TOT*DD];
__device__ __nv_bfloat16 g_Kh[M_TOT*DD];
__device__ __nv_bfloat16 g_Kl[M_TOT*DD];
__device__ __nv_bfloat16 g_Vh[M_TOT*DD];
__device__ __nv_bfloat16 g_Vl[M_TOT*DD];
__device__ float2 g_rope[TT*(DD/2)];   // cos/sin table [t][pair]

// ---------------------------------------------------------------------------
// Warp-MMA helpers (sm_80+ baseline PTX — legal on plain sm_100 target)
// ---------------------------------------------------------------------------
__device__ __forceinline__ uint32_t smem_u32(const void* p) {
    uint32_t a;
    asm("{ .reg .u64 t; cvta.to.shared.u64 t, %1; cvt.u32.u64 %0, t; }" : "=r"(a) : "l"(p));
    return a;
}
__device__ __forceinline__ void ldmx4(uint32_t* r, uint32_t addr) {
    asm volatile("ldmatrix.sync.aligned.m8n8.x4.shared.b16 {%0,%1,%2,%3}, [%4];"
        : "=r"(r[0]), "=r"(r[1]), "=r"(r[2]), "=r"(r[3]) : "r"(addr));
}
__device__ __forceinline__ void ldmx4t(uint32_t* r, uint32_t addr) {
    asm volatile("ldmatrix.sync.aligned.m8n8.x4.trans.shared.b16 {%0,%1,%2,%3}, [%4];"
        : "=r"(r[0]), "=r"(r[1]), "=r"(r[2]), "=r"(r[3]) : "r"(addr));
}
__device__ __forceinline__ void mma_bf16(float* c, const uint32_t* a, const uint32_t* b) {
    asm volatile("mma.sync.aligned.m16n8k16.row.col.f32.bf16.bf16.f32 "
        "{%0,%1,%2,%3}, {%4,%5,%6,%7}, {%8,%9}, {%0,%1,%2,%3};"
        : "+f"(c[0]), "+f"(c[1]), "+f"(c[2]), "+f"(c[3])
        : "r"(a[0]), "r"(a[1]), "r"(a[2]), "r"(a[3]), "r"(b[0]), "r"(b[1]));
}
#define CP16(dst, src) \
    asm volatile("cp.async.cg.shared.global [%0], [%1], 16;" :: "r"(dst), "l"(src))
#define CPCOMMIT() asm volatile("cp.async.commit_group;" ::: "memory")
#define CPWAIT1()  asm volatile("cp.async.wait_group 1;" ::: "memory")
#define CPWAIT0()  asm volatile("cp.async.wait_group 0;" ::: "memory")

__device__ __forceinline__ void split4(float4 v, uint2& hi, uint2& lo) {
    float f[4] = {v.x, v.y, v.z, v.w};
    unsigned short h[4], l[4];
#pragma unroll
    for (int i = 0; i < 4; i++) {
        __nv_bfloat16 bh = __float2bfloat16(f[i]);
        h[i] = __bfloat16_as_ushort(bh);
        float r = f[i] - __bfloat162float(bh);
        l[i] = __bfloat16_as_ushort(__float2bfloat16(r));
    }
    hi.x = (uint32_t)h[0] | ((uint32_t)h[1] << 16);
    hi.y = (uint32_t)h[2] | ((uint32_t)h[3] << 16);
    lo.x = (uint32_t)l[0] | ((uint32_t)l[1] << 16);
    lo.y = (uint32_t)l[2] | ((uint32_t)l[3] << 16);
}
__device__ __forceinline__ uint32_t pack2h(float a, float b, uint32_t& lo) {
    __nv_bfloat16 ah = __float2bfloat16(a), bh = __float2bfloat16(b);
    float ar = a - __bfloat162float(ah), br = b - __bfloat162float(bh);
    lo = (uint32_t)__bfloat16_as_ushort(__float2bfloat16(ar))
       | ((uint32_t)__bfloat16_as_ushort(__float2bfloat16(br)) << 16);
    return (uint32_t)__bfloat16_as_ushort(ah) | ((uint32_t)__bfloat16_as_ushort(bh) << 16);
}

// swizzled byte offset inside a 128-col bf16 tile (256 B rows)
__device__ __forceinline__ uint32_t swz(uint32_t row, uint32_t col) {
    return row*256u + ((((col>>3) ^ (row&7)))<<4) + (col&7)*2u;
}

// ---------------------------------------------------------------------------
// RoPE table
// ---------------------------------------------------------------------------
__global__ __launch_bounds__(256)
void rope_table_kernel()
{
    int idx = blockIdx.x * blockDim.x + threadIdx.x;
    if (idx >= TT * (DD/2)) return;
    int i = idx & 63;
    int t = idx >> 6;
    float freq = exp2f(-0.20762050593046777f * (float)i);
    float ang = (float)t * freq;
    float s, c;
    sincosf(ang, &s, &c);
    g_rope[idx] = make_float2(c, s);
}

// ===========================================================================
// Projection via mma.sync bf16 3-term split; RoPE fused; writes split bf16.
// Q additionally pre-scaled by 1/sqrt(d) (folded out of attention).
// ===========================================================================
#define STR 40
#define TILE_ELEMS (128*STR)
#define STAGE_ELEMS (4*TILE_ELEMS)
#define PROJ_SMEM_BYTES (2*STAGE_ELEMS*2)

extern __shared__ char proj_sm[];

__global__ __launch_bounds__(256)
void proj_mma_kernel(const float* __restrict__ X,
                     const float* __restrict__ wQ,
                     const float* __restrict__ wK,
                     const float* __restrict__ wV)
{
    const int tid  = threadIdx.x;
    const int wid  = tid >> 5;
    const int lane = tid & 31;
    const int m0   = blockIdx.x * 128;
    const int wsel = blockIdx.y;
    const float* W = (wsel == 0) ? wQ : (wsel == 1) ? wK : wV;
    __nv_bfloat16* oh = (wsel == 0) ? g_Qh : (wsel == 1) ? g_Kh : g_Vh;
    __nv_bfloat16* ol = (wsel == 0) ? g_Ql : (wsel == 1) ? g_Kl : g_Vl;

    const int wm = wid >> 1;
    const int wn = wid & 1;

    const uint32_t sbase = smem_u32(proj_sm);
    __nv_bfloat16* sm16 = reinterpret_cast<__nv_bfloat16*>(proj_sm);

    const int lrow  = tid >> 1;
    const int lhalf = tid & 1;

    float4 px[2][4], pw[2][4];
#pragma unroll
    for (int j = 0; j < 4; j++) {
        px[0][j] = *reinterpret_cast<const float4*>(&X[(size_t)(m0 + lrow) * EE + 16*lhalf + 4*j]);
        pw[0][j] = *reinterpret_cast<const float4*>(&W[(size_t)lrow * EE + 16*lhalf + 4*j]);
    }

    float acc[2][8][4];
#pragma unroll
    for (int mf = 0; mf < 2; mf++)
#pragma unroll
        for (int nf = 0; nf < 8; nf++)
#pragma unroll
            for (int q = 0; q < 4; q++) acc[mf][nf][q] = 0.f;

    for (int c = 0; c < 32; c++) {
        const int buf = c & 1;
        __nv_bfloat16* Ah = sm16 + buf * STAGE_ELEMS;
        __nv_bfloat16* Al = Ah + TILE_ELEMS;
        __nv_bfloat16* Bh = Ah + 2*TILE_ELEMS;
        __nv_bfloat16* Bl = Ah + 3*TILE_ELEMS;

#pragma unroll
        for (int j = 0; j < 4; j++) {
            const int col = 16*lhalf + 4*j;
            uint2 hi, lo;
            split4(px[buf][j], hi, lo);
            *reinterpret_cast<uint2*>(&Ah[lrow*STR + col]) = hi;
            *reinterpret_cast<uint2*>(&Al[lrow*STR + col]) = lo;
            split4(pw[buf][j], hi, lo);
            *reinterpret_cast<uint2*>(&Bh[lrow*STR + col]) = hi;
            *reinterpret_cast<uint2*>(&Bl[lrow*STR + col]) = lo;
        }

        if (c + 1 < 32) {
            const int k0 = (c + 1) * 32;
            const int nb = (c + 1) & 1;
#pragma unroll
            for (int j = 0; j < 4; j++) {
                px[nb][j] = *reinterpret_cast<const float4*>(&X[(size_t)(m0 + lrow) * EE + k0 + 16*lhalf + 4*j]);
                pw[nb][j] = *reinterpret_cast<const float4*>(&W[(size_t)lrow * EE + k0 + 16*lhalf + 4*j]);
            }
        }

        __syncthreads();

        const uint32_t stage = sbase + buf * (STAGE_ELEMS * 2);
#pragma unroll
        for (int kb = 0; kb < 32; kb += 16) {
            uint32_t ah[2][4], al[2][4];
#pragma unroll
            for (int mf = 0; mf < 2; mf++) {
                const int row = 32*wm + 16*mf + (lane & 15);
                const int col = kb + 8*(lane >> 4);
                const uint32_t addrA = stage + (uint32_t)(row*STR + col) * 2;
                ldmx4(ah[mf], addrA);
                ldmx4(al[mf], addrA + TILE_ELEMS*2);
            }
            uint32_t bh[8][2], bl[8][2];
#pragma unroll
            for (int nb4 = 0; nb4 < 4; nb4++) {
                const int n   = 64*wn + 16*nb4 + (lane & 7) + ((lane & 16) >> 1);
                const int col = kb + (lane & 8);
                const uint32_t addrB = stage + (uint32_t)(2*TILE_ELEMS + n*STR + col) * 2;
                uint32_t r[4];
                ldmx4(r, addrB);
                bh[2*nb4][0] = r[0]; bh[2*nb4][1] = r[1];
                bh[2*nb4+1][0] = r[2]; bh[2*nb4+1][1] = r[3];
                ldmx4(r, addrB + TILE_ELEMS*2);
                bl[2*nb4][0] = r[0]; bl[2*nb4][1] = r[1];
                bl[2*nb4+1][0] = r[2]; bl[2*nb4+1][1] = r[3];
            }
#pragma unroll
            for (int mf = 0; mf < 2; mf++)
#pragma unroll
                for (int nf = 0; nf < 8; nf++) {
                    mma_bf16(acc[mf][nf], ah[mf], bh[nf]);
                    mma_bf16(acc[mf][nf], ah[mf], bl[nf]);
                    mma_bf16(acc[mf][nf], al[mf], bh[nf]);
                }
        }
        __syncthreads();
    }

    // epilogue: RoPE (Q/K), Q pre-scale, split, store bf16 h/l
    const bool do_rope = (wsel < 2);
    const bool do_scale = (wsel == 0);
#pragma unroll
    for (int mf = 0; mf < 2; mf++) {
#pragma unroll
        for (int half = 0; half < 2; half++) {
            const int row = m0 + 32*wm + 16*mf + (lane >> 2) + 8*half;
            const int t = row & (TT - 1);
#pragma unroll
            for (int nf = 0; nf < 8; nf++) {
                const int col = 64*wn + 8*nf + 2*(lane & 3);
                float x0 = acc[mf][nf][2*half];
                float x1 = acc[mf][nf][2*half + 1];
                if (do_rope) {
                    float2 cs = g_rope[t * 64 + (col >> 1)];
                    float r0 = x0 * cs.x - x1 * cs.y;
                    float r1 = x0 * cs.y + x1 * cs.x;
                    x0 = r0; x1 = r1;
                }
                if (do_scale) { x0 *= SCALE; x1 *= SCALE; }
                uint32_t lo;
                uint32_t hi = pack2h(x0, x1, lo);
                *reinterpret_cast<uint32_t*>(&oh[(size_t)row * DD + col]) = hi;
                *reinterpret_cast<uint32_t*>(&ol[(size_t)row * DD + col]) = lo;
            }
        }
    }
}

// ===========================================================================
// Tensor-core flash attention, P-in-registers formulation.
// BM=32, BN=64, 256 threads = 8 warps; warp (wm, wk).
// Each warp: 16 q-rows (wm) x its 16-key slice (wk); S C-frags pack directly
// into PV A-frags (no P smem round-trip, no intra-tile barrier).
// Partial O (16x128 fp32/warp) reduced across wk once per q-tile via the
// then-idle K/V smem area. Unnormalized exp (Q pre-scaled), register row sums.
// ===========================================================================
#define A_QH 0                 // Q hi staging (8 KB)
#define A_QL 8192              // Q lo staging (8 KB)
#define A_K  16384             // K h/l double buf (2 x 32 KB); O-partial scratch at q-tile end
#define A_V  81920             // V h/l double buf (2 x 32 KB)
#define A_SUM 147456           // 512 B
#define ATTN_SMEM 147968
#define PART_ROW 528           // O-partial row stride (132 floats, conflict-free)
#define PART_REG 8448          // 16*528 per warp

extern __shared__ char attn_smc[];

__device__ __forceinline__ void issue_kv(uint32_t sb, int buf, int tid,
                                         const __nv_bfloat16* Kh, const __nv_bfloat16* Kl,
                                         const __nv_bfloat16* Vh, const __nv_bfloat16* Vl,
                                         int kbase)
{
    const int row = tid >> 2;            // 0..63
    const int ch0 = (tid & 3) * 4;
    const size_t gb = ((size_t)(kbase + row)) * DD;
    const uint32_t kb = sb + A_K + buf * 32768;
    const uint32_t vb = sb + A_V + buf * 32768;
#pragma unroll
    for (int j = 0; j < 4; j++) {
        const int ch = ch0 + j;
        const uint32_t d = swz(row, ch * 8);
        CP16(kb + d,         Kh + gb + ch*8);
        CP16(kb + 16384 + d, Kl + gb + ch*8);
        CP16(vb + d,         Vh + gb + ch*8);
        CP16(vb + 16384 + d, Vl + gb + ch*8);
    }
}

__global__ __launch_bounds__(256)
void attn_mma_kernel(float* __restrict__ out)
{
    const uint32_t sb = smem_u32(attn_smc);
    const int tid  = threadIdx.x;
    const int wid  = tid >> 5;
    const int lane = tid & 31;
    const int wm   = wid >> 2;           // 0..1: M half (16 rows)
    const int wk   = wid & 3;            // 0..3: 16-key slice
    const int b    = blockIdx.x >> 5;
    const int pb   = blockIdx.x & 31;

    const __nv_bfloat16* Qh = g_Qh + (size_t)b*TT*DD;
    const __nv_bfloat16* Ql = g_Ql + (size_t)b*TT*DD;
    const __nv_bfloat16* Kh = g_Kh + (size_t)b*TT*DD;
    const __nv_bfloat16* Kl = g_Kl + (size_t)b*TT*DD;
    const __nv_bfloat16* Vh = g_Vh + (size_t)b*TT*DD;
    const __nv_bfloat16* Vl = g_Vl + (size_t)b*TT*DD;

    float* sums = reinterpret_cast<float*>(attn_smc + A_SUM);

    for (int sel = 0; sel < 2; sel++) {
        const int q0 = (sel ? (63 - pb) : pb) * 32;
        const int ntiles = q0 / 64 + 1;

        // stage Q tile (h/l) into swizzled smem
        {
            const int row = tid >> 3;            // 0..31
            const int cb  = (tid & 7) * 2;
#pragma unroll
            for (int j = 0; j < 2; j++) {
                const int ch = cb + j;
                const size_t gq = ((size_t)(q0 + row)) * DD + ch*8;
                const uint32_t d = swz(row, ch * 8);
                *reinterpret_cast<uint4*>(attn_smc + A_QH + d) =
                    *reinterpret_cast<const uint4*>(Qh + gq);
                *reinterpret_cast<uint4*>(attn_smc + A_QL + d) =
                    *reinterpret_cast<const uint4*>(Ql + gq);
            }
        }
        issue_kv(sb, 0, tid, Kh, Kl, Vh, Vl, 0);
        CPCOMMIT();
        if (ntiles > 1) issue_kv(sb, 1, tid, Kh, Kl, Vh, Vl, 64);
        CPCOMMIT();
        __syncthreads();

        // hoist Q fragments into registers (whole K-dim, h+l)
        uint32_t qfh[8][4], qfl[8][4];
        {
            const int aRow = 16*wm + (lane & 15);
            const int aCol = 8 * (lane >> 4);
#pragma unroll
            for (int kc = 0; kc < 8; kc++) {
                const uint32_t a = swz(aRow, kc*16 + aCol);
                ldmx4(qfh[kc], sb + A_QH + a);
                ldmx4(qfl[kc], sb + A_QL + a);
            }
        }

        float lsum[2] = {0.f, 0.f};
        float O[16][4];
#pragma unroll
        for (int nf = 0; nf < 16; nf++)
#pragma unroll
            for (int q = 0; q < 4; q++) O[nf][q] = 0.f;

        for (int t = 0; t < ntiles; t++) {
            const int buf = t & 1;
            const int kbase = t * 64;
            const uint32_t kBufH = sb + A_K + buf*32768;
            const uint32_t kBufL = kBufH + 16384;
            const uint32_t vBufH = sb + A_V + buf*32768;
            const uint32_t vBufL = vBufH + 16384;

            CPWAIT1();
            __syncthreads();

            // ---- S = Qh*Kh + Qh*Kl + Ql*Kh (Q from regs) ----
            float S[2][4];
#pragma unroll
            for (int nf = 0; nf < 2; nf++)
#pragma unroll
                for (int q = 0; q < 4; q++) S[nf][q] = 0.f;

            const int bRow = 16*wk + (lane & 7) + ((lane & 16) >> 1);
            const int bCol = lane & 8;
#pragma unroll
            for (int kc = 0; kc < 8; kc++) {
                uint32_t rb[4], kbh[2][2], kbl[2][2];
                const uint32_t ba = swz(bRow, kc*16 + bCol);
                ldmx4(rb, kBufH + ba);
                kbh[0][0]=rb[0]; kbh[0][1]=rb[1]; kbh[1][0]=rb[2]; kbh[1][1]=rb[3];
                ldmx4(rb, kBufL + ba);
                kbl[0][0]=rb[0]; kbl[0][1]=rb[1]; kbl[1][0]=rb[2]; kbl[1][1]=rb[3];
#pragma unroll
                for (int nf = 0; nf < 2; nf++) {
                    mma_bf16(S[nf], qfh[kc], kbh[nf]);
                    mma_bf16(S[nf], qfh[kc], kbl[nf]);
                    mma_bf16(S[nf], qfl[kc], kbh[nf]);
                }
            }

            // ---- p = exp(s) (masked -> 0); pack C-frags directly to PV A-frags ----
            const bool lastt = (t == ntiles - 1);
            uint32_t pfh[4], pfl[4];
#pragma unroll
            for (int nf = 0; nf < 2; nf++)
#pragma unroll
                for (int h = 0; h < 2; h++) {
                    const int gcol0 = kbase + 16*wk + 8*nf + 2*(lane & 3);
                    const int grow  = q0 + 16*wm + (lane >> 2) + 8*h;
                    float p0 = (lastt && gcol0     > grow) ? 0.f : __expf(S[nf][2*h]);
                    float p1 = (lastt && gcol0 + 1 > grow) ? 0.f : __expf(S[nf][2*h+1]);
                    lsum[h] += p0 + p1;
                    uint32_t lo;
                    uint32_t hi = pack2h(p0, p1, lo);
                    pfh[nf*2 + h] = hi;   // a0..a3 layout: (S[0],h0)(S[0],h1)(S[1],h0)(S[1],h1)
                    pfl[nf*2 + h] = lo;
                }

            // ---- O += Ph*Vh + Ph*Vl + Pl*Vh  (warp's 16 keys x all 128 D) ----
            const int key = 16*wk + (lane & 15);
            const int dc8 = 8 * (lane >> 4);
#pragma unroll
            for (int j = 0; j < 8; j++) {
                uint32_t r[4];
                const uint32_t va = swz(key, 16*j + dc8);
                ldmx4t(r, vBufH + va);
                uint32_t vbh0[2] = {r[0], r[1]};
                uint32_t vbh1[2] = {r[2], r[3]};
                ldmx4t(r, vBufL + va);
                uint32_t vbl0[2] = {r[0], r[1]};
                uint32_t vbl1[2] = {r[2], r[3]};
                mma_bf16(O[2*j],   pfh, vbh0);
                mma_bf16(O[2*j],   pfh, vbl0);
                mma_bf16(O[2*j],   pfl, vbh0);
                mma_bf16(O[2*j+1], pfh, vbh1);
                mma_bf16(O[2*j+1], pfh, vbl1);
                mma_bf16(O[2*j+1], pfl, vbh1);
            }

            __syncthreads();
            if (t + 2 < ntiles) issue_kv(sb, buf, tid, Kh, Kl, Vh, Vl, (t + 2) * 64);
            CPCOMMIT();
        }

        // ---- row-sum partials ----
#pragma unroll
        for (int h = 0; h < 2; h++) {
            float v = lsum[h];
            v += __shfl_xor_sync(0xffffffff, v, 1);
            v += __shfl_xor_sync(0xffffffff, v, 2);
            if ((lane & 3) == 0)
                sums[(16*wm + (lane >> 2) + 8*h)*4 + wk] = v;
        }

        // ---- drain cp.async; reuse K/V area for O-partial reduction ----
        CPWAIT0();
        __syncthreads();
        {
            char* preg = attn_smc + A_K + wid * PART_REG;
            const int r0 = lane >> 2;
#pragma unroll
            for (int nf = 0; nf < 16; nf++) {
                const int col = 8*nf + 2*(lane & 3);
                *reinterpret_cast<float2*>(preg + r0*PART_ROW + col*4) =
                    make_float2(O[nf][0], O[nf][1]);
                *reinterpret_cast<float2*>(preg + (r0+8)*PART_ROW + col*4) =
                    make_float2(O[nf][2], O[nf][3]);
            }
        }
        __syncthreads();
        {
            const int rr  = tid >> 3;            // 0..31 (q row)
            const int cc  = (tid & 7) * 16;      // col base (floats)
            const int wmh = rr >> 4;
            const int lr  = rr & 15;
            float4 sp = *reinterpret_cast<float4*>(&sums[rr*4]);
            const float inv = 1.f / ((sp.x + sp.y) + (sp.z + sp.w));
            const size_t ob = ((size_t)(b*TT + q0 + rr)) * DD + cc;
#pragma unroll
            for (int s4 = 0; s4 < 4; s4++) {
                float4 a = make_float4(0.f, 0.f, 0.f, 0.f);
#pragma unroll
                for (int k = 0; k < 4; k++) {
                    const float4 v = *reinterpret_cast<const float4*>(
                        attn_smc + A_K + (wmh*4 + k)*PART_REG + lr*PART_ROW + (cc + s4*4)*4);
                    a.x += v.x; a.y += v.y; a.z += v.z; a.w += v.w;
                }
                *reinterpret_cast<float4*>(&out[ob + s4*4]) =
                    make_float4(a.x*inv, a.y*inv, a.z*inv, a.w*inv);
            }
        }
        __syncthreads();
    }
}

// ---------------------------------------------------------------------------
extern "C" void kernel_launch(void* const* d_in, const int* in_sizes, int n_in,
                              void* d_out, int out_size)
{
    const float* X  = (const float*)d_in[0];
    const float* wQ = (const float*)d_in[1];
    const float* wK = (const float*)d_in[2];
    const float* wV = (const float*)d_in[3];
    float* out = (float*)d_out;

    cudaFuncSetAttribute(proj_mma_kernel, cudaFuncAttributeMaxDynamicSharedMemorySize,
                         PROJ_SMEM_BYTES);
    cudaFuncSetAttribute(attn_mma_kernel, cudaFuncAttributeMaxDynamicSharedMemorySize,
                         ATTN_SMEM);

    rope_table_kernel<<<(TT * (DD/2) + 255) / 256, 256>>>();
    proj_mma_kernel<<<dim3(M_TOT / 128, 3), 256, PROJ_SMEM_BYTES>>>(X, wQ, wK, wV);
    attn_mma_kernel<<<BB * 32, 256, ATTN_SMEM>>>(out);
}

// round 14
// speedup vs baseline: 7.3591x; 1.1832x over previous
#include <cuda_runtime.h>
#include <cuda_bf16.h>
#include <cuda_fp16.h>
#include <cstdint>
#include <math.h>
#include <math_constants.h>

#define BB 4
#define TT 2048
#define EE 1024
#define DD 128
#define M_TOT (BB*TT)
#define SCALE 0.08838834764831845f

// fp16 operands (written by proj, read by attention). 2 MB each.
__device__ __half g_Q16[M_TOT*DD];
__device__ __half g_K16[M_TOT*DD];
__device__ __half g_V16[M_TOT*DD];
__device__ float2 g_rope[TT*(DD/2)];   // cos/sin table [t][pair]

// ---------------------------------------------------------------------------
// Warp-MMA helpers (sm_80+ baseline PTX — legal on plain sm_100 target)
// ---------------------------------------------------------------------------
__device__ __forceinline__ uint32_t smem_u32(const void* p) {
    uint32_t a;
    asm("{ .reg .u64 t; cvta.to.shared.u64 t, %1; cvt.u32.u64 %0, t; }" : "=r"(a) : "l"(p));
    return a;
}
__device__ __forceinline__ void ldmx4(uint32_t* r, uint32_t addr) {
    asm volatile("ldmatrix.sync.aligned.m8n8.x4.shared.b16 {%0,%1,%2,%3}, [%4];"
        : "=r"(r[0]), "=r"(r[1]), "=r"(r[2]), "=r"(r[3]) : "r"(addr));
}
__device__ __forceinline__ void ldmx4t(uint32_t* r, uint32_t addr) {
    asm volatile("ldmatrix.sync.aligned.m8n8.x4.trans.shared.b16 {%0,%1,%2,%3}, [%4];"
        : "=r"(r[0]), "=r"(r[1]), "=r"(r[2]), "=r"(r[3]) : "r"(addr));
}
__device__ __forceinline__ void mma_bf16(float* c, const uint32_t* a, const uint32_t* b) {
    asm volatile("mma.sync.aligned.m16n8k16.row.col.f32.bf16.bf16.f32 "
        "{%0,%1,%2,%3}, {%4,%5,%6,%7}, {%8,%9}, {%0,%1,%2,%3};"
        : "+f"(c[0]), "+f"(c[1]), "+f"(c[2]), "+f"(c[3])
        : "r"(a[0]), "r"(a[1]), "r"(a[2]), "r"(a[3]), "r"(b[0]), "r"(b[1]));
}
__device__ __forceinline__ void mma_f16(float* c, const uint32_t* a, const uint32_t* b) {
    asm volatile("mma.sync.aligned.m16n8k16.row.col.f32.f16.f16.f32 "
        "{%0,%1,%2,%3}, {%4,%5,%6,%7}, {%8,%9}, {%0,%1,%2,%3};"
        : "+f"(c[0]), "+f"(c[1]), "+f"(c[2]), "+f"(c[3])
        : "r"(a[0]), "r"(a[1]), "r"(a[2]), "r"(a[3]), "r"(b[0]), "r"(b[1]));
}
#define CP16(dst, src) \
    asm volatile("cp.async.cg.shared.global [%0], [%1], 16;" :: "r"(dst), "l"(src))
#define CPCOMMIT() asm volatile("cp.async.commit_group;" ::: "memory")
#define CPWAIT1()  asm volatile("cp.async.wait_group 1;" ::: "memory")
#define CPWAIT0()  asm volatile("cp.async.wait_group 0;" ::: "memory")

__device__ __forceinline__ void split4(float4 v, uint2& hi, uint2& lo) {
    float f[4] = {v.x, v.y, v.z, v.w};
    unsigned short h[4], l[4];
#pragma unroll
    for (int i = 0; i < 4; i++) {
        __nv_bfloat16 bh = __float2bfloat16(f[i]);
        h[i] = __bfloat16_as_ushort(bh);
        float r = f[i] - __bfloat162float(bh);
        l[i] = __bfloat16_as_ushort(__float2bfloat16(r));
    }
    hi.x = (uint32_t)h[0] | ((uint32_t)h[1] << 16);
    hi.y = (uint32_t)h[2] | ((uint32_t)h[3] << 16);
    lo.x = (uint32_t)l[0] | ((uint32_t)l[1] << 16);
    lo.y = (uint32_t)l[2] | ((uint32_t)l[3] << 16);
}
__device__ __forceinline__ uint32_t pack_h2(float a, float b) {
    __half2 h = __floats2half2_rn(a, b);
    return *reinterpret_cast<uint32_t*>(&h);
}

// swizzled byte offset inside a 128-col 16-bit tile (256 B rows)
__device__ __forceinline__ uint32_t swz(uint32_t row, uint32_t col) {
    return row*256u + ((((col>>3) ^ (row&7)))<<4) + (col&7)*2u;
}

// ---------------------------------------------------------------------------
// RoPE table
// ---------------------------------------------------------------------------
__global__ __launch_bounds__(256)
void rope_table_kernel()
{
    int idx = blockIdx.x * blockDim.x + threadIdx.x;
    if (idx >= TT * (DD/2)) return;
    int i = idx & 63;
    int t = idx >> 6;
    float freq = exp2f(-0.20762050593046777f * (float)i);
    float ang = (float)t * freq;
    float s, c;
    sincosf(ang, &s, &c);
    g_rope[idx] = make_float2(c, s);
}

// ===========================================================================
// Projection via mma.sync bf16 3-term split; RoPE fused; writes fp16.
// Q additionally pre-scaled by 1/sqrt(d) (folded out of attention).
// ===========================================================================
#define STR 40
#define TILE_ELEMS (128*STR)
#define STAGE_ELEMS (4*TILE_ELEMS)
#define PROJ_SMEM_BYTES (2*STAGE_ELEMS*2)

extern __shared__ char proj_sm[];

__global__ __launch_bounds__(256)
void proj_mma_kernel(const float* __restrict__ X,
                     const float* __restrict__ wQ,
                     const float* __restrict__ wK,
                     const float* __restrict__ wV)
{
    const int tid  = threadIdx.x;
    const int wid  = tid >> 5;
    const int lane = tid & 31;
    const int m0   = blockIdx.x * 128;
    const int wsel = blockIdx.y;
    const float* W = (wsel == 0) ? wQ : (wsel == 1) ? wK : wV;
    __half* o16    = (wsel == 0) ? g_Q16 : (wsel == 1) ? g_K16 : g_V16;

    const int wm = wid >> 1;
    const int wn = wid & 1;

    const uint32_t sbase = smem_u32(proj_sm);
    __nv_bfloat16* sm16 = reinterpret_cast<__nv_bfloat16*>(proj_sm);

    const int lrow  = tid >> 1;
    const int lhalf = tid & 1;

    float4 px[2][4], pw[2][4];
#pragma unroll
    for (int j = 0; j < 4; j++) {
        px[0][j] = *reinterpret_cast<const float4*>(&X[(size_t)(m0 + lrow) * EE + 16*lhalf + 4*j]);
        pw[0][j] = *reinterpret_cast<const float4*>(&W[(size_t)lrow * EE + 16*lhalf + 4*j]);
    }

    float acc[2][8][4];
#pragma unroll
    for (int mf = 0; mf < 2; mf++)
#pragma unroll
        for (int nf = 0; nf < 8; nf++)
#pragma unroll
            for (int q = 0; q < 4; q++) acc[mf][nf][q] = 0.f;

    for (int c = 0; c < 32; c++) {
        const int buf = c & 1;
        __nv_bfloat16* Ah = sm16 + buf * STAGE_ELEMS;
        __nv_bfloat16* Al = Ah + TILE_ELEMS;
        __nv_bfloat16* Bh = Ah + 2*TILE_ELEMS;
        __nv_bfloat16* Bl = Ah + 3*TILE_ELEMS;

#pragma unroll
        for (int j = 0; j < 4; j++) {
            const int col = 16*lhalf + 4*j;
            uint2 hi, lo;
            split4(px[buf][j], hi, lo);
            *reinterpret_cast<uint2*>(&Ah[lrow*STR + col]) = hi;
            *reinterpret_cast<uint2*>(&Al[lrow*STR + col]) = lo;
            split4(pw[buf][j], hi, lo);
            *reinterpret_cast<uint2*>(&Bh[lrow*STR + col]) = hi;
            *reinterpret_cast<uint2*>(&Bl[lrow*STR + col]) = lo;
        }

        if (c + 1 < 32) {
            const int k0 = (c + 1) * 32;
            const int nb = (c + 1) & 1;
#pragma unroll
            for (int j = 0; j < 4; j++) {
                px[nb][j] = *reinterpret_cast<const float4*>(&X[(size_t)(m0 + lrow) * EE + k0 + 16*lhalf + 4*j]);
                pw[nb][j] = *reinterpret_cast<const float4*>(&W[(size_t)lrow * EE + k0 + 16*lhalf + 4*j]);
            }
        }

        __syncthreads();

        const uint32_t stage = sbase + buf * (STAGE_ELEMS * 2);
#pragma unroll
        for (int kb = 0; kb < 32; kb += 16) {
            uint32_t ah[2][4], al[2][4];
#pragma unroll
            for (int mf = 0; mf < 2; mf++) {
                const int row = 32*wm + 16*mf + (lane & 15);
                const int col = kb + 8*(lane >> 4);
                const uint32_t addrA = stage + (uint32_t)(row*STR + col) * 2;
                ldmx4(ah[mf], addrA);
                ldmx4(al[mf], addrA + TILE_ELEMS*2);
            }
            uint32_t bh[8][2], bl[8][2];
#pragma unroll
            for (int nb4 = 0; nb4 < 4; nb4++) {
                const int n   = 64*wn + 16*nb4 + (lane & 7) + ((lane & 16) >> 1);
                const int col = kb + (lane & 8);
                const uint32_t addrB = stage + (uint32_t)(2*TILE_ELEMS + n*STR + col) * 2;
                uint32_t r[4];
                ldmx4(r, addrB);
                bh[2*nb4][0] = r[0]; bh[2*nb4][1] = r[1];
                bh[2*nb4+1][0] = r[2]; bh[2*nb4+1][1] = r[3];
                ldmx4(r, addrB + TILE_ELEMS*2);
                bl[2*nb4][0] = r[0]; bl[2*nb4][1] = r[1];
                bl[2*nb4+1][0] = r[2]; bl[2*nb4+1][1] = r[3];
            }
#pragma unroll
            for (int mf = 0; mf < 2; mf++)
#pragma unroll
                for (int nf = 0; nf < 8; nf++) {
                    mma_bf16(acc[mf][nf], ah[mf], bh[nf]);
                    mma_bf16(acc[mf][nf], ah[mf], bl[nf]);
                    mma_bf16(acc[mf][nf], al[mf], bh[nf]);
                }
        }
        __syncthreads();
    }

    // epilogue: RoPE (Q/K), Q pre-scale, fp16 store
    const bool do_rope = (wsel < 2);
    const bool do_scale = (wsel == 0);
#pragma unroll
    for (int mf = 0; mf < 2; mf++) {
#pragma unroll
        for (int half = 0; half < 2; half++) {
            const int row = m0 + 32*wm + 16*mf + (lane >> 2) + 8*half;
            const int t = row & (TT - 1);
#pragma unroll
            for (int nf = 0; nf < 8; nf++) {
                const int col = 64*wn + 8*nf + 2*(lane & 3);
                float x0 = acc[mf][nf][2*half];
                float x1 = acc[mf][nf][2*half + 1];
                if (do_rope) {
                    float2 cs = g_rope[t * 64 + (col >> 1)];
                    float r0 = x0 * cs.x - x1 * cs.y;
                    float r1 = x0 * cs.y + x1 * cs.x;
                    x0 = r0; x1 = r1;
                }
                if (do_scale) { x0 *= SCALE; x1 *= SCALE; }
                *reinterpret_cast<uint32_t*>(&o16[(size_t)row * DD + col]) = pack_h2(x0, x1);
            }
        }
    }
}

// ===========================================================================
// Tensor-core flash attention, single-term fp16, P-in-registers.
// BM=32, BN=64, 256 threads = 8 warps; warp (wm, wk).
// S = Q·K (fp16, fp32 acc); P = exp(S) packed directly to PV A-frags;
// O partials (16x128/warp) reduced across wk once per q-tile.
// ===========================================================================
#define A_Q  0                 // Q fp16 staging (8 KB)
#define A_K  8192              // K double buf (2 x 16 KB)
#define A_V  40960             // V double buf (2 x 16 KB) -> ends 73728
#define A_PART 8192            // O-partial scratch (overlaps K/V; 8 x 8448 = 67584 -> ends 75776)
#define A_SUM 75776            // 512 B
#define ATTN_SMEM 76288
#define PART_ROW 528           // O-partial row stride (132 floats)
#define PART_REG 8448          // 16*528 per warp

extern __shared__ char attn_smc[];

__device__ __forceinline__ void issue_kv(uint32_t sb, int buf, int tid,
                                         const __half* Kp, const __half* Vp,
                                         int kbase)
{
    const int row = tid >> 2;            // 0..63
    const int ch0 = (tid & 3) * 4;
    const size_t gb = ((size_t)(kbase + row)) * DD;
    const uint32_t kb = sb + A_K + buf * 16384;
    const uint32_t vb = sb + A_V + buf * 16384;
#pragma unroll
    for (int j = 0; j < 4; j++) {
        const int ch = ch0 + j;
        const uint32_t d = swz(row, ch * 8);
        CP16(kb + d, Kp + gb + ch*8);
        CP16(vb + d, Vp + gb + ch*8);
    }
}

__global__ __launch_bounds__(256)
void attn_mma_kernel(float* __restrict__ out)
{
    const uint32_t sb = smem_u32(attn_smc);
    const int tid  = threadIdx.x;
    const int wid  = tid >> 5;
    const int lane = tid & 31;
    const int wm   = wid >> 2;           // 0..1: M half (16 rows)
    const int wk   = wid & 3;            // 0..3: 16-key slice
    const int b    = blockIdx.x >> 5;
    const int pb   = blockIdx.x & 31;

    const __half* Qp = g_Q16 + (size_t)b*TT*DD;
    const __half* Kp = g_K16 + (size_t)b*TT*DD;
    const __half* Vp = g_V16 + (size_t)b*TT*DD;

    float* sums = reinterpret_cast<float*>(attn_smc + A_SUM);

    for (int sel = 0; sel < 2; sel++) {
        const int q0 = (sel ? (63 - pb) : pb) * 32;
        const int ntiles = q0 / 64 + 1;

        // stage Q tile into swizzled smem
        {
            const int row = tid >> 3;            // 0..31
            const int cb  = (tid & 7) * 2;
#pragma unroll
            for (int j = 0; j < 2; j++) {
                const int ch = cb + j;
                const size_t gq = ((size_t)(q0 + row)) * DD + ch*8;
                *reinterpret_cast<uint4*>(attn_smc + A_Q + swz(row, ch*8)) =
                    *reinterpret_cast<const uint4*>(Qp + gq);
            }
        }
        issue_kv(sb, 0, tid, Kp, Vp, 0);
        CPCOMMIT();
        if (ntiles > 1) issue_kv(sb, 1, tid, Kp, Vp, 64);
        CPCOMMIT();
        __syncthreads();

        // hoist Q fragments into registers (whole K-dim)
        uint32_t qf[8][4];
        {
            const int aRow = 16*wm + (lane & 15);
            const int aCol = 8 * (lane >> 4);
#pragma unroll
            for (int kc = 0; kc < 8; kc++)
                ldmx4(qf[kc], sb + A_Q + swz(aRow, kc*16 + aCol));
        }

        float lsum[2] = {0.f, 0.f};
        float O[16][4];
#pragma unroll
        for (int nf = 0; nf < 16; nf++)
#pragma unroll
            for (int q = 0; q < 4; q++) O[nf][q] = 0.f;

        for (int t = 0; t < ntiles; t++) {
            const int buf = t & 1;
            const int kbase = t * 64;
            const uint32_t kBuf = sb + A_K + buf*16384;
            const uint32_t vBuf = sb + A_V + buf*16384;

            CPWAIT1();
            __syncthreads();

            // ---- S = Q @ K^T (fp16 single-term) ----
            float S[2][4];
#pragma unroll
            for (int nf = 0; nf < 2; nf++)
#pragma unroll
                for (int q = 0; q < 4; q++) S[nf][q] = 0.f;

            const int bRow = 16*wk + (lane & 7) + ((lane & 16) >> 1);
            const int bCol = lane & 8;
#pragma unroll
            for (int kc = 0; kc < 8; kc++) {
                uint32_t rb[4];
                ldmx4(rb, kBuf + swz(bRow, kc*16 + bCol));
                uint32_t kb0[2] = {rb[0], rb[1]};
                uint32_t kb1[2] = {rb[2], rb[3]};
                mma_f16(S[0], qf[kc], kb0);
                mma_f16(S[1], qf[kc], kb1);
            }

            // ---- p = exp(s) (masked -> 0); pack C-frags directly to PV A-frags ----
            const bool lastt = (t == ntiles - 1);
            uint32_t pf[4];
#pragma unroll
            for (int nf = 0; nf < 2; nf++)
#pragma unroll
                for (int h = 0; h < 2; h++) {
                    const int gcol0 = kbase + 16*wk + 8*nf + 2*(lane & 3);
                    const int grow  = q0 + 16*wm + (lane >> 2) + 8*h;
                    float p0 = (lastt && gcol0     > grow) ? 0.f : __expf(S[nf][2*h]);
                    float p1 = (lastt && gcol0 + 1 > grow) ? 0.f : __expf(S[nf][2*h+1]);
                    lsum[h] += p0 + p1;
                    pf[nf*2 + h] = pack_h2(p0, p1);
                }

            // ---- O += P @ V  (warp's 16 keys x all 128 D) ----
            const int key = 16*wk + (lane & 15);
            const int dc8 = 8 * (lane >> 4);
#pragma unroll
            for (int j = 0; j < 8; j++) {
                uint32_t r[4];
                ldmx4t(r, vBuf + swz(key, 16*j + dc8));
                uint32_t vb0[2] = {r[0], r[1]};
                uint32_t vb1[2] = {r[2], r[3]};
                mma_f16(O[2*j],   pf, vb0);
                mma_f16(O[2*j+1], pf, vb1);
            }

            __syncthreads();
            if (t + 2 < ntiles) issue_kv(sb, buf, tid, Kp, Vp, (t + 2) * 64);
            CPCOMMIT();
        }

        // ---- row-sum partials ----
#pragma unroll
        for (int h = 0; h < 2; h++) {
            float v = lsum[h];
            v += __shfl_xor_sync(0xffffffff, v, 1);
            v += __shfl_xor_sync(0xffffffff, v, 2);
            if ((lane & 3) == 0)
                sums[(16*wm + (lane >> 2) + 8*h)*4 + wk] = v;
        }

        // ---- drain cp.async; reuse K/V area for O-partial reduction ----
        CPWAIT0();
        __syncthreads();
        {
            char* preg = attn_smc + A_PART + wid * PART_REG;
            const int r0 = lane >> 2;
#pragma unroll
            for (int nf = 0; nf < 16; nf++) {
                const int col = 8*nf + 2*(lane & 3);
                *reinterpret_cast<float2*>(preg + r0*PART_ROW + col*4) =
                    make_float2(O[nf][0], O[nf][1]);
                *reinterpret_cast<float2*>(preg + (r0+8)*PART_ROW + col*4) =
                    make_float2(O[nf][2], O[nf][3]);
            }
        }
        __syncthreads();
        {
            const int rr  = tid >> 3;            // 0..31 (q row)
            const int cc  = (tid & 7) * 16;      // col base (floats)
            const int wmh = rr >> 4;
            const int lr  = rr & 15;
            float4 sp = *reinterpret_cast<float4*>(&sums[rr*4]);
            const float inv = 1.f / ((sp.x + sp.y) + (sp.z + sp.w));
            const size_t ob = ((size_t)(b*TT + q0 + rr)) * DD + cc;
#pragma unroll
            for (int s4 = 0; s4 < 4; s4++) {
                float4 a = make_float4(0.f, 0.f, 0.f, 0.f);
#pragma unroll
                for (int k = 0; k < 4; k++) {
                    const float4 v = *reinterpret_cast<const float4*>(
                        attn_smc + A_PART + (wmh*4 + k)*PART_REG + lr*PART_ROW + (cc + s4*4)*4);
                    a.x += v.x; a.y += v.y; a.z += v.z; a.w += v.w;
                }
                *reinterpret_cast<float4*>(&out[ob + s4*4]) =
                    make_float4(a.x*inv, a.y*inv, a.z*inv, a.w*inv);
            }
        }
        __syncthreads();
    }
}

// ---------------------------------------------------------------------------
extern "C" void kernel_launch(void* const* d_in, const int* in_sizes, int n_in,
                              void* d_out, int out_size)
{
    const float* X  = (const float*)d_in[0];
    const float* wQ = (const float*)d_in[1];
    const float* wK = (const float*)d_in[2];
    const float* wV = (const float*)d_in[3];
    float* out = (float*)d_out;

    cudaFuncSetAttribute(proj_mma_kernel, cudaFuncAttributeMaxDynamicSharedMemorySize,
                         PROJ_SMEM_BYTES);
    cudaFuncSetAttribute(attn_mma_kernel, cudaFuncAttributeMaxDynamicSharedMemorySize,
                         ATTN_SMEM);

    rope_table_kernel<<<(TT * (DD/2) + 255) / 256, 256>>>();
    proj_mma_kernel<<<dim3(M_TOT / 128, 3), 256, PROJ_SMEM_BYTES>>>(X, wQ, wK, wV);
    attn_mma_kernel<<<BB * 32, 256, ATTN_SMEM>>>(out);
}

// round 15
// speedup vs baseline: 8.8247x; 1.1992x over previous
#include <cuda_runtime.h>
#include <cuda_bf16.h>
#include <cuda_fp16.h>
#include <cstdint>
#include <math.h>
#include <math_constants.h>

#define BB 4
#define TT 2048
#define EE 1024
#define DD 128
#define M_TOT (BB*TT)
#define SCALE 0.08838834764831845f

// fp16 operands (written by proj, read by attention). 2 MB each.
__device__ __half g_Q16[M_TOT*DD];
__device__ __half g_K16[M_TOT*DD];
__device__ __half g_V16[M_TOT*DD];
__device__ float2 g_rope[TT*(DD/2)];   // cos/sin table [t][pair]

// ---------------------------------------------------------------------------
// Warp-MMA helpers (sm_80+ baseline PTX — legal on plain sm_100 target)
// ---------------------------------------------------------------------------
__device__ __forceinline__ uint32_t smem_u32(const void* p) {
    uint32_t a;
    asm("{ .reg .u64 t; cvta.to.shared.u64 t, %1; cvt.u32.u64 %0, t; }" : "=r"(a) : "l"(p));
    return a;
}
__device__ __forceinline__ void ldmx4(uint32_t* r, uint32_t addr) {
    asm volatile("ldmatrix.sync.aligned.m8n8.x4.shared.b16 {%0,%1,%2,%3}, [%4];"
        : "=r"(r[0]), "=r"(r[1]), "=r"(r[2]), "=r"(r[3]) : "r"(addr));
}
__device__ __forceinline__ void ldmx4t(uint32_t* r, uint32_t addr) {
    asm volatile("ldmatrix.sync.aligned.m8n8.x4.trans.shared.b16 {%0,%1,%2,%3}, [%4];"
        : "=r"(r[0]), "=r"(r[1]), "=r"(r[2]), "=r"(r[3]) : "r"(addr));
}
__device__ __forceinline__ void mma_bf16(float* c, const uint32_t* a, const uint32_t* b) {
    asm volatile("mma.sync.aligned.m16n8k16.row.col.f32.bf16.bf16.f32 "
        "{%0,%1,%2,%3}, {%4,%5,%6,%7}, {%8,%9}, {%0,%1,%2,%3};"
        : "+f"(c[0]), "+f"(c[1]), "+f"(c[2]), "+f"(c[3])
        : "r"(a[0]), "r"(a[1]), "r"(a[2]), "r"(a[3]), "r"(b[0]), "r"(b[1]));
}
__device__ __forceinline__ void mma_f16(float* c, const uint32_t* a, const uint32_t* b) {
    asm volatile("mma.sync.aligned.m16n8k16.row.col.f32.f16.f16.f32 "
        "{%0,%1,%2,%3}, {%4,%5,%6,%7}, {%8,%9}, {%0,%1,%2,%3};"
        : "+f"(c[0]), "+f"(c[1]), "+f"(c[2]), "+f"(c[3])
        : "r"(a[0]), "r"(a[1]), "r"(a[2]), "r"(a[3]), "r"(b[0]), "r"(b[1]));
}
#define CP16(dst, src) \
    asm volatile("cp.async.cg.shared.global [%0], [%1], 16;" :: "r"(dst), "l"(src))
#define CPCOMMIT() asm volatile("cp.async.commit_group;" ::: "memory")
#define CPWAIT1()  asm volatile("cp.async.wait_group 1;" ::: "memory")
#define CPWAIT0()  asm volatile("cp.async.wait_group 0;" ::: "memory")

__device__ __forceinline__ void split4(float4 v, uint2& hi, uint2& lo) {
    float f[4] = {v.x, v.y, v.z, v.w};
    unsigned short h[4], l[4];
#pragma unroll
    for (int i = 0; i < 4; i++) {
        __nv_bfloat16 bh = __float2bfloat16(f[i]);
        h[i] = __bfloat16_as_ushort(bh);
        float r = f[i] - __bfloat162float(bh);
        l[i] = __bfloat16_as_ushort(__float2bfloat16(r));
    }
    hi.x = (uint32_t)h[0] | ((uint32_t)h[1] << 16);
    hi.y = (uint32_t)h[2] | ((uint32_t)h[3] << 16);
    lo.x = (uint32_t)l[0] | ((uint32_t)l[1] << 16);
    lo.y = (uint32_t)l[2] | ((uint32_t)l[3] << 16);
}
__device__ __forceinline__ uint32_t pack_h2(float a, float b) {
    __half2 h = __floats2half2_rn(a, b);
    return *reinterpret_cast<uint32_t*>(&h);
}

// swizzled byte offset inside a 128-col 16-bit tile (256 B rows)
__device__ __forceinline__ uint32_t swz(uint32_t row, uint32_t col) {
    return row*256u + ((((col>>3) ^ (row&7)))<<4) + (col&7)*2u;
}

// ---------------------------------------------------------------------------
// RoPE table
// ---------------------------------------------------------------------------
__global__ __launch_bounds__(256)
void rope_table_kernel()
{
    int idx = blockIdx.x * blockDim.x + threadIdx.x;
    if (idx >= TT * (DD/2)) return;
    int i = idx & 63;
    int t = idx >> 6;
    float freq = exp2f(-0.20762050593046777f * (float)i);
    float ang = (float)t * freq;
    float s, c;
    sincosf(ang, &s, &c);
    g_rope[idx] = make_float2(c, s);
}

// ===========================================================================
// Projection via mma.sync bf16 3-term split; RoPE fused; writes fp16.
// BM=64 (half-size CTAs -> grid 384 for better wave packing on 148 SMs).
// 8 warps: wm in {0,1} (32 rows), wn in {0..3} (32 cols). BK=32 double-buf.
// ===========================================================================
#define STR 40
#define TILE_A (64*STR)                 // 2560 elems
#define TILE_B (128*STR)                // 5120 elems
#define STAGE_ELEMS (2*TILE_A + 2*TILE_B)   // 15360
#define OFF_AL (TILE_A*2)               // byte offsets within a stage
#define OFF_BH (2*TILE_A*2)
#define OFF_BL ((2*TILE_A + TILE_B)*2)
#define PROJ_SMEM_BYTES (2*STAGE_ELEMS*2)   // 61440 B

extern __shared__ char proj_sm[];

__global__ __launch_bounds__(256)
void proj_mma_kernel(const float* __restrict__ X,
                     const float* __restrict__ wQ,
                     const float* __restrict__ wK,
                     const float* __restrict__ wV)
{
    const int tid  = threadIdx.x;
    const int wid  = tid >> 5;
    const int lane = tid & 31;
    const int m0   = blockIdx.x * 64;
    const int wsel = blockIdx.y;
    const float* W = (wsel == 0) ? wQ : (wsel == 1) ? wK : wV;
    __half* o16    = (wsel == 0) ? g_Q16 : (wsel == 1) ? g_K16 : g_V16;

    const int wm = wid >> 2;   // 0..1 -> M offset 32*wm
    const int wn = wid & 3;    // 0..3 -> N offset 32*wn

    const uint32_t sbase = smem_u32(proj_sm);
    __nv_bfloat16* sm16 = reinterpret_cast<__nv_bfloat16*>(proj_sm);

    // loaders: A covers 64 rows x 32 cols; B covers 128 rows x 32 cols
    const int arow = tid >> 2;          // 0..63
    const int acb  = (tid & 3) * 8;     // col base (2 float4)
    const int brow = tid >> 1;          // 0..127
    const int bcb  = (tid & 1) * 16;    // col base (4 float4)

    float4 px[2][2], pw[2][4];
#pragma unroll
    for (int j = 0; j < 2; j++)
        px[0][j] = *reinterpret_cast<const float4*>(&X[(size_t)(m0 + arow) * EE + acb + 4*j]);
#pragma unroll
    for (int j = 0; j < 4; j++)
        pw[0][j] = *reinterpret_cast<const float4*>(&W[(size_t)brow * EE + bcb + 4*j]);

    float acc[2][4][4];
#pragma unroll
    for (int mf = 0; mf < 2; mf++)
#pragma unroll
        for (int nf = 0; nf < 4; nf++)
#pragma unroll
            for (int q = 0; q < 4; q++) acc[mf][nf][q] = 0.f;

    for (int c = 0; c < 32; c++) {
        const int buf = c & 1;
        __nv_bfloat16* Ah = sm16 + buf * STAGE_ELEMS;
        __nv_bfloat16* Al = Ah + TILE_A;
        __nv_bfloat16* Bh = Ah + 2*TILE_A;
        __nv_bfloat16* Bl = Bh + TILE_B;

#pragma unroll
        for (int j = 0; j < 2; j++) {
            const int col = acb + 4*j;
            uint2 hi, lo;
            split4(px[buf][j], hi, lo);
            *reinterpret_cast<uint2*>(&Ah[arow*STR + col]) = hi;
            *reinterpret_cast<uint2*>(&Al[arow*STR + col]) = lo;
        }
#pragma unroll
        for (int j = 0; j < 4; j++) {
            const int col = bcb + 4*j;
            uint2 hi, lo;
            split4(pw[buf][j], hi, lo);
            *reinterpret_cast<uint2*>(&Bh[brow*STR + col]) = hi;
            *reinterpret_cast<uint2*>(&Bl[brow*STR + col]) = lo;
        }

        if (c + 1 < 32) {
            const int k0 = (c + 1) * 32;
            const int nb = (c + 1) & 1;
#pragma unroll
            for (int j = 0; j < 2; j++)
                px[nb][j] = *reinterpret_cast<const float4*>(&X[(size_t)(m0 + arow) * EE + k0 + acb + 4*j]);
#pragma unroll
            for (int j = 0; j < 4; j++)
                pw[nb][j] = *reinterpret_cast<const float4*>(&W[(size_t)brow * EE + k0 + bcb + 4*j]);
        }

        __syncthreads();

        const uint32_t stage = sbase + buf * (STAGE_ELEMS * 2);
#pragma unroll
        for (int kb = 0; kb < 32; kb += 16) {
            uint32_t ah[2][4], al[2][4];
#pragma unroll
            for (int mf = 0; mf < 2; mf++) {
                const int row = 32*wm + 16*mf + (lane & 15);
                const int col = kb + 8*(lane >> 4);
                const uint32_t addrA = stage + (uint32_t)(row*STR + col) * 2;
                ldmx4(ah[mf], addrA);
                ldmx4(al[mf], addrA + OFF_AL);
            }
            uint32_t bh[4][2], bl[4][2];
#pragma unroll
            for (int nb4 = 0; nb4 < 2; nb4++) {
                const int n   = 32*wn + 16*nb4 + (lane & 7) + ((lane & 16) >> 1);
                const int col = kb + (lane & 8);
                const uint32_t addrB = stage + OFF_BH + (uint32_t)(n*STR + col) * 2;
                uint32_t r[4];
                ldmx4(r, addrB);
                bh[2*nb4][0] = r[0]; bh[2*nb4][1] = r[1];
                bh[2*nb4+1][0] = r[2]; bh[2*nb4+1][1] = r[3];
                ldmx4(r, addrB + (OFF_BL - OFF_BH));
                bl[2*nb4][0] = r[0]; bl[2*nb4][1] = r[1];
                bl[2*nb4+1][0] = r[2]; bl[2*nb4+1][1] = r[3];
            }
#pragma unroll
            for (int mf = 0; mf < 2; mf++)
#pragma unroll
                for (int nf = 0; nf < 4; nf++) {
                    mma_bf16(acc[mf][nf], ah[mf], bh[nf]);
                    mma_bf16(acc[mf][nf], ah[mf], bl[nf]);
                    mma_bf16(acc[mf][nf], al[mf], bh[nf]);
                }
        }
        __syncthreads();
    }

    // epilogue: RoPE (Q/K), Q pre-scale, fp16 store
    const bool do_rope = (wsel < 2);
    const bool do_scale = (wsel == 0);
#pragma unroll
    for (int mf = 0; mf < 2; mf++) {
#pragma unroll
        for (int half = 0; half < 2; half++) {
            const int row = m0 + 32*wm + 16*mf + (lane >> 2) + 8*half;
            const int t = row & (TT - 1);
#pragma unroll
            for (int nf = 0; nf < 4; nf++) {
                const int col = 32*wn + 8*nf + 2*(lane & 3);
                float x0 = acc[mf][nf][2*half];
                float x1 = acc[mf][nf][2*half + 1];
                if (do_rope) {
                    float2 cs = g_rope[t * 64 + (col >> 1)];
                    float r0 = x0 * cs.x - x1 * cs.y;
                    float r1 = x0 * cs.y + x1 * cs.x;
                    x0 = r0; x1 = r1;
                }
                if (do_scale) { x0 *= SCALE; x1 *= SCALE; }
                *reinterpret_cast<uint32_t*>(&o16[(size_t)row * DD + col]) = pack_h2(x0, x1);
            }
        }
    }
}

// ===========================================================================
// Tensor-core flash attention, single-term fp16, P-in-registers.
// 256 CTAs (one 32-row q-tile each), big-first order, batches interleaved.
// ===========================================================================
#define A_Q  0                 // Q fp16 staging (8 KB)
#define A_K  8192              // K double buf (2 x 16 KB)
#define A_V  40960             // V double buf (2 x 16 KB) -> ends 73728
#define A_PART 8192            // O-partial scratch (overlaps K/V; 8 x 8448 = 67584 -> ends 75776)
#define A_SUM 75776            // 512 B
#define ATTN_SMEM 76288
#define PART_ROW 528           // O-partial row stride (132 floats)
#define PART_REG 8448          // 16*528 per warp

extern __shared__ char attn_smc[];

__device__ __forceinline__ void issue_kv(uint32_t sb, int buf, int tid,
                                         const __half* Kp, const __half* Vp,
                                         int kbase)
{
    const int row = tid >> 2;            // 0..63
    const int ch0 = (tid & 3) * 4;
    const size_t gb = ((size_t)(kbase + row)) * DD;
    const uint32_t kb = sb + A_K + buf * 16384;
    const uint32_t vb = sb + A_V + buf * 16384;
#pragma unroll
    for (int j = 0; j < 4; j++) {
        const int ch = ch0 + j;
        const uint32_t d = swz(row, ch * 8);
        CP16(kb + d, Kp + gb + ch*8);
        CP16(vb + d, Vp + gb + ch*8);
    }
}

__global__ __launch_bounds__(256)
void attn_mma_kernel(float* __restrict__ out)
{
    const uint32_t sb = smem_u32(attn_smc);
    const int tid  = threadIdx.x;
    const int wid  = tid >> 5;
    const int lane = tid & 31;
    const int wm   = wid >> 2;           // 0..1: M half (16 rows)
    const int wk   = wid & 3;            // 0..3: 16-key slice
    const int b    = blockIdx.x & 3;     // batches interleaved
    const int qt   = 63 - (blockIdx.x >> 2);   // big-first

    const __half* Qp = g_Q16 + (size_t)b*TT*DD;
    const __half* Kp = g_K16 + (size_t)b*TT*DD;
    const __half* Vp = g_V16 + (size_t)b*TT*DD;

    float* sums = reinterpret_cast<float*>(attn_smc + A_SUM);

    const int q0 = qt * 32;
    const int ntiles = q0 / 64 + 1;

    // stage Q tile into swizzled smem
    {
        const int row = tid >> 3;            // 0..31
        const int cb  = (tid & 7) * 2;
#pragma unroll
        for (int j = 0; j < 2; j++) {
            const int ch = cb + j;
            const size_t gq = ((size_t)(q0 + row)) * DD + ch*8;
            *reinterpret_cast<uint4*>(attn_smc + A_Q + swz(row, ch*8)) =
                *reinterpret_cast<const uint4*>(Qp + gq);
        }
    }
    issue_kv(sb, 0, tid, Kp, Vp, 0);
    CPCOMMIT();
    if (ntiles > 1) issue_kv(sb, 1, tid, Kp, Vp, 64);
    CPCOMMIT();
    __syncthreads();

    // hoist Q fragments into registers (whole K-dim)
    uint32_t qf[8][4];
    {
        const int aRow = 16*wm + (lane & 15);
        const int aCol = 8 * (lane >> 4);
#pragma unroll
        for (int kc = 0; kc < 8; kc++)
            ldmx4(qf[kc], sb + A_Q + swz(aRow, kc*16 + aCol));
    }

    float lsum[2] = {0.f, 0.f};
    float O[16][4];
#pragma unroll
    for (int nf = 0; nf < 16; nf++)
#pragma unroll
        for (int q = 0; q < 4; q++) O[nf][q] = 0.f;

    for (int t = 0; t < ntiles; t++) {
        const int buf = t & 1;
        const int kbase = t * 64;
        const uint32_t kBuf = sb + A_K + buf*16384;
        const uint32_t vBuf = sb + A_V + buf*16384;

        CPWAIT1();
        __syncthreads();

        // ---- S = Q @ K^T (fp16 single-term) ----
        float S[2][4];
#pragma unroll
        for (int nf = 0; nf < 2; nf++)
#pragma unroll
            for (int q = 0; q < 4; q++) S[nf][q] = 0.f;

        const int bRow = 16*wk + (lane & 7) + ((lane & 16) >> 1);
        const int bCol = lane & 8;
#pragma unroll
        for (int kc = 0; kc < 8; kc++) {
            uint32_t rb[4];
            ldmx4(rb, kBuf + swz(bRow, kc*16 + bCol));
            uint32_t kb0[2] = {rb[0], rb[1]};
            uint32_t kb1[2] = {rb[2], rb[3]};
            mma_f16(S[0], qf[kc], kb0);
            mma_f16(S[1], qf[kc], kb1);
        }

        // ---- p = exp(s) (masked -> 0); pack C-frags directly to PV A-frags ----
        const bool lastt = (t == ntiles - 1);
        uint32_t pf[4];
#pragma unroll
        for (int nf = 0; nf < 2; nf++)
#pragma unroll
            for (int h = 0; h < 2; h++) {
                const int gcol0 = kbase + 16*wk + 8*nf + 2*(lane & 3);
                const int grow  = q0 + 16*wm + (lane >> 2) + 8*h;
                float p0 = (lastt && gcol0     > grow) ? 0.f : __expf(S[nf][2*h]);
                float p1 = (lastt && gcol0 + 1 > grow) ? 0.f : __expf(S[nf][2*h+1]);
                lsum[h] += p0 + p1;
                pf[nf*2 + h] = pack_h2(p0, p1);
            }

        // ---- O += P @ V  (warp's 16 keys x all 128 D) ----
        const int key = 16*wk + (lane & 15);
        const int dc8 = 8 * (lane >> 4);
#pragma unroll
        for (int j = 0; j < 8; j++) {
            uint32_t r[4];
            ldmx4t(r, vBuf + swz(key, 16*j + dc8));
            uint32_t vb0[2] = {r[0], r[1]};
            uint32_t vb1[2] = {r[2], r[3]};
            mma_f16(O[2*j],   pf, vb0);
            mma_f16(O[2*j+1], pf, vb1);
        }

        __syncthreads();
        if (t + 2 < ntiles) issue_kv(sb, buf, tid, Kp, Vp, (t + 2) * 64);
        CPCOMMIT();
    }

    // ---- row-sum partials ----
#pragma unroll
    for (int h = 0; h < 2; h++) {
        float v = lsum[h];
        v += __shfl_xor_sync(0xffffffff, v, 1);
        v += __shfl_xor_sync(0xffffffff, v, 2);
        if ((lane & 3) == 0)
            sums[(16*wm + (lane >> 2) + 8*h)*4 + wk] = v;
    }

    // ---- drain cp.async; reuse K/V area for O-partial reduction ----
    CPWAIT0();
    __syncthreads();
    {
        char* preg = attn_smc + A_PART + wid * PART_REG;
        const int r0 = lane >> 2;
#pragma unroll
        for (int nf = 0; nf < 16; nf++) {
            const int col = 8*nf + 2*(lane & 3);
            *reinterpret_cast<float2*>(preg + r0*PART_ROW + col*4) =
                make_float2(O[nf][0], O[nf][1]);
            *reinterpret_cast<float2*>(preg + (r0+8)*PART_ROW + col*4) =
                make_float2(O[nf][2], O[nf][3]);
        }
    }
    __syncthreads();
    {
        const int rr  = tid >> 3;            // 0..31 (q row)
        const int cc  = (tid & 7) * 16;      // col base (floats)
        const int wmh = rr >> 4;
        const int lr  = rr & 15;
        float4 sp = *reinterpret_cast<float4*>(&sums[rr*4]);
        const float inv = 1.f / ((sp.x + sp.y) + (sp.z + sp.w));
        const size_t ob = ((size_t)(b*TT + q0 + rr)) * DD + cc;
#pragma unroll
        for (int s4 = 0; s4 < 4; s4++) {
            float4 a = make_float4(0.f, 0.f, 0.f, 0.f);
#pragma unroll
            for (int k = 0; k < 4; k++) {
                const float4 v = *reinterpret_cast<const float4*>(
                    attn_smc + A_PART + (wmh*4 + k)*PART_REG + lr*PART_ROW + (cc + s4*4)*4);
                a.x += v.x; a.y += v.y; a.z += v.z; a.w += v.w;
            }
            *reinterpret_cast<float4*>(&out[ob + s4*4]) =
                make_float4(a.x*inv, a.y*inv, a.z*inv, a.w*inv);
        }
    }
}

// ---------------------------------------------------------------------------
extern "C" void kernel_launch(void* const* d_in, const int* in_sizes, int n_in,
                              void* d_out, int out_size)
{
    const float* X  = (const float*)d_in[0];
    const float* wQ = (const float*)d_in[1];
    const float* wK = (const float*)d_in[2];
    const float* wV = (const float*)d_in[3];
    float* out = (float*)d_out;

    cudaFuncSetAttribute(proj_mma_kernel, cudaFuncAttributeMaxDynamicSharedMemorySize,
                         PROJ_SMEM_BYTES);
    cudaFuncSetAttribute(attn_mma_kernel, cudaFuncAttributeMaxDynamicSharedMemorySize,
                         ATTN_SMEM);

    rope_table_kernel<<<(TT * (DD/2) + 255) / 256, 256>>>();
    proj_mma_kernel<<<dim3(M_TOT / 64, 3), 256, PROJ_SMEM_BYTES>>>(X, wQ, wK, wV);
    attn_mma_kernel<<<BB * 64, 256, ATTN_SMEM>>>(out);
}